// round 1
// baseline (speedup 1.0000x reference)
#include <cuda_runtime.h>
#include <math.h>

// Batched expm of sl(3) elements:
//   A = sum_k v_k * G_k  (3x3, traceless by construction)
//   H = expm(A);  H /= H[2][2];  out = float(H)
//
// fp64 scaling-and-squaring, Paterson-Stockmeyer degree-11 Taylor (5 matmuls)
// + s squarings with s = ceil(log2(||A||_inf)) so scaled norm <= 1.

__device__ __forceinline__ void mm3(const double* __restrict__ a,
                                    const double* __restrict__ b,
                                    double* __restrict__ c) {
#pragma unroll
    for (int i = 0; i < 3; i++) {
#pragma unroll
        for (int j = 0; j < 3; j++) {
            double s = a[i * 3 + 0] * b[0 * 3 + j];
            s = fma(a[i * 3 + 1], b[1 * 3 + j], s);
            s = fma(a[i * 3 + 2], b[2 * 3 + j], s);
            c[i * 3 + j] = s;
        }
    }
}

__global__ void __launch_bounds__(128)
lie_expm_kernel(const float* __restrict__ lie, float* __restrict__ out, int n) {
    int i = blockIdx.x * blockDim.x + threadIdx.x;
    if (i >= n) return;

    // 8 coefficients, coalesced as two float4 loads.
    const float4* vp = reinterpret_cast<const float4*>(lie) + 2 * (size_t)i;
    float4 v0 = vp[0];
    float4 v1 = vp[1];

    double x  = (double)v0.x;  // e0: x translation  -> A[0][2]
    double y  = (double)v0.y;  // e1: y translation  -> A[1][2]
    double r  = (double)v0.z;  // e2: rotation
    double sc = (double)v0.w;  // e3: scale (trace-free)
    double st = (double)v1.x;  // e4: stretch
    double sh = (double)v1.y;  // e5: shear
    double kx = (double)v1.z;  // e6: x keystone -> A[2][0]
    double ky = (double)v1.w;  // e7: y keystone -> A[2][1]

    double A[9];
    A[0] = sc + st;  A[1] = sh - r;   A[2] = x;
    A[3] = sh + r;   A[4] = sc - st;  A[5] = y;
    A[6] = kx;       A[7] = ky;       A[8] = -2.0 * sc;

    // inf-norm
    double r0 = fabs(A[0]) + fabs(A[1]) + fabs(A[2]);
    double r1 = fabs(A[3]) + fabs(A[4]) + fabs(A[5]);
    double r2 = fabs(A[6]) + fabs(A[7]) + fabs(A[8]);
    double nrm = fmax(r0, fmax(r1, r2));

    // s = ceil(log2(nrm)) for nrm > 1 (frexp: nrm = f*2^e, f in [0.5,1))
    int s = 0;
    if (nrm > 1.0) {
        int e;
        frexp(nrm, &e);
        s = e;
    }
    double scl = ldexp(1.0, -s);
#pragma unroll
    for (int k = 0; k < 9; k++) A[k] *= scl;

    double A2[9], A3[9];
    mm3(A, A, A2);
    mm3(A2, A, A3);

    // Inverse factorials
    const double c2  = 1.0 / 2.0;
    const double c3  = 1.0 / 6.0;
    const double c4  = 1.0 / 24.0;
    const double c5  = 1.0 / 120.0;
    const double c6  = 1.0 / 720.0;
    const double c7  = 1.0 / 5040.0;
    const double c8  = 1.0 / 40320.0;
    const double c9  = 1.0 / 362880.0;
    const double c10 = 1.0 / 3628800.0;
    const double c11 = 1.0 / 39916800.0;

    double P[9], T[9];

    // P = C3 = c9*I + c10*A + c11*A2
#pragma unroll
    for (int k = 0; k < 9; k++) P[k] = fma(c10, A[k], c11 * A2[k]);
    P[0] += c9; P[4] += c9; P[8] += c9;

    // P = P*A3 + C2   (C2 = c6*I + c7*A + c8*A2)
    mm3(P, A3, T);
#pragma unroll
    for (int k = 0; k < 9; k++) P[k] = fma(c7, A[k], fma(c8, A2[k], T[k]));
    P[0] += c6; P[4] += c6; P[8] += c6;

    // P = P*A3 + C1   (C1 = c3*I + c4*A + c5*A2)
    mm3(P, A3, T);
#pragma unroll
    for (int k = 0; k < 9; k++) P[k] = fma(c4, A[k], fma(c5, A2[k], T[k]));
    P[0] += c3; P[4] += c3; P[8] += c3;

    // P = P*A3 + C0   (C0 = I + A + c2*A2)
    mm3(P, A3, T);
#pragma unroll
    for (int k = 0; k < 9; k++) P[k] = fma(c2, A2[k], T[k] + A[k]);
    P[0] += 1.0; P[4] += 1.0; P[8] += 1.0;

    // Squaring phase: H = P^(2^s)
    for (int q = 0; q < s; q++) {
        mm3(P, P, T);
#pragma unroll
        for (int k = 0; k < 9; k++) P[k] = T[k];
    }

    // Homogeneous normalization by H[2][2]
    double inv = 1.0 / P[8];
    float* o = out + 9 * (size_t)i;
#pragma unroll
    for (int k = 0; k < 9; k++) o[k] = (float)(P[k] * inv);
}

extern "C" void kernel_launch(void* const* d_in, const int* in_sizes, int n_in,
                              void* d_out, int out_size) {
    const float* lie = (const float*)d_in[0];
    float* out = (float*)d_out;
    int n = in_sizes[0] / 8;  // (B, 8) float32
    int threads = 128;
    int blocks = (n + threads - 1) / threads;
    lie_expm_kernel<<<blocks, threads>>>(lie, out, n);
}

// round 3
// speedup vs baseline: 3.6311x; 3.6311x over previous
#include <cuda_runtime.h>
#include <math.h>

// Hybrid-precision batched expm of sl(3) elements:
//   Pass 1 (fp32): scaling-and-squaring, PS degree-11 Taylor. Flags samples
//     whose fp32 result is untrustworthy (large ||A|| or near-zero H[2][2])
//     into a compacted index list.
//   Pass 2 (fp64): recomputes only the flagged samples.

#define MAXB (1 << 20)
__device__ int g_count;
__device__ int g_flag_idx[MAXB];

// ---------------- fp64 path ----------------
__device__ __forceinline__ void mm3d(const double* __restrict__ a,
                                     const double* __restrict__ b,
                                     double* __restrict__ c) {
#pragma unroll
    for (int i = 0; i < 3; i++)
#pragma unroll
        for (int j = 0; j < 3; j++) {
            double s = a[i * 3] * b[j];
            s = fma(a[i * 3 + 1], b[3 + j], s);
            s = fma(a[i * 3 + 2], b[6 + j], s);
            c[i * 3 + j] = s;
        }
}

__device__ void expm_f64(const float* __restrict__ lie, float* __restrict__ out,
                         long long i) {
    const float4* vp = reinterpret_cast<const float4*>(lie) + 2 * i;
    float4 v0 = vp[0];
    float4 v1 = vp[1];

    double x = (double)v0.x, y = (double)v0.y, r = (double)v0.z, sc = (double)v0.w;
    double st = (double)v1.x, sh = (double)v1.y, kx = (double)v1.z, ky = (double)v1.w;

    double A[9];
    A[0] = sc + st;  A[1] = sh - r;   A[2] = x;
    A[3] = sh + r;   A[4] = sc - st;  A[5] = y;
    A[6] = kx;       A[7] = ky;       A[8] = -2.0 * sc;

    double r0 = fabs(A[0]) + fabs(A[1]) + fabs(A[2]);
    double r1 = fabs(A[3]) + fabs(A[4]) + fabs(A[5]);
    double r2 = fabs(A[6]) + fabs(A[7]) + fabs(A[8]);
    double nrm = fmax(r0, fmax(r1, r2));

    int s = 0;
    if (nrm > 1.0) { int e; frexp(nrm, &e); s = e; }
    double scl = ldexp(1.0, -s);
#pragma unroll
    for (int k = 0; k < 9; k++) A[k] *= scl;

    double A2[9], A3[9];
    mm3d(A, A, A2);
    mm3d(A2, A, A3);

    const double c2 = 1.0 / 2, c3 = 1.0 / 6, c4 = 1.0 / 24, c5 = 1.0 / 120;
    const double c6 = 1.0 / 720, c7 = 1.0 / 5040, c8 = 1.0 / 40320;
    const double c9 = 1.0 / 362880, c10 = 1.0 / 3628800, c11 = 1.0 / 39916800;

    double P[9], T[9];
#pragma unroll
    for (int k = 0; k < 9; k++) P[k] = fma(c10, A[k], c11 * A2[k]);
    P[0] += c9; P[4] += c9; P[8] += c9;

    mm3d(P, A3, T);
#pragma unroll
    for (int k = 0; k < 9; k++) P[k] = fma(c7, A[k], fma(c8, A2[k], T[k]));
    P[0] += c6; P[4] += c6; P[8] += c6;

    mm3d(P, A3, T);
#pragma unroll
    for (int k = 0; k < 9; k++) P[k] = fma(c4, A[k], fma(c5, A2[k], T[k]));
    P[0] += c3; P[4] += c3; P[8] += c3;

    mm3d(P, A3, T);
#pragma unroll
    for (int k = 0; k < 9; k++) P[k] = fma(c2, A2[k], T[k] + A[k]);
    P[0] += 1.0; P[4] += 1.0; P[8] += 1.0;

    for (int q = 0; q < s; q++) {
        mm3d(P, P, T);
#pragma unroll
        for (int k = 0; k < 9; k++) P[k] = T[k];
    }

    double inv = 1.0 / P[8];
    float* o = out + 9 * i;
#pragma unroll
    for (int k = 0; k < 9; k++) o[k] = (float)(P[k] * inv);
}

// ---------------- fp32 path ----------------
__device__ __forceinline__ void mm3f(const float* __restrict__ a,
                                     const float* __restrict__ b,
                                     float* __restrict__ c) {
#pragma unroll
    for (int i = 0; i < 3; i++)
#pragma unroll
        for (int j = 0; j < 3; j++) {
            float s = a[i * 3] * b[j];
            s = fmaf(a[i * 3 + 1], b[3 + j], s);
            s = fmaf(a[i * 3 + 2], b[6 + j], s);
            c[i * 3 + j] = s;
        }
}

__global__ void __launch_bounds__(256)
zero_count_kernel() { g_count = 0; }

__global__ void __launch_bounds__(256)
pass1_f32_kernel(const float* __restrict__ lie, float* __restrict__ out, int n) {
    int i = blockIdx.x * blockDim.x + threadIdx.x;
    if (i >= n) return;

    const float4* vp = reinterpret_cast<const float4*>(lie) + 2 * (size_t)i;
    float4 v0 = vp[0];
    float4 v1 = vp[1];

    float x = v0.x, y = v0.y, r = v0.z, sc = v0.w;
    float st = v1.x, sh = v1.y, kx = v1.z, ky = v1.w;

    float A[9];
    A[0] = sc + st;  A[1] = sh - r;   A[2] = x;
    A[3] = sh + r;   A[4] = sc - st;  A[5] = y;
    A[6] = kx;       A[7] = ky;       A[8] = -2.0f * sc;

    float r0 = fabsf(A[0]) + fabsf(A[1]) + fabsf(A[2]);
    float r1 = fabsf(A[3]) + fabsf(A[4]) + fabsf(A[5]);
    float r2 = fabsf(A[6]) + fabsf(A[7]) + fabsf(A[8]);
    float nrm = fmaxf(r0, fmaxf(r1, r2));

    int s = 0;
    if (nrm > 1.0f) { int e; frexpf(nrm, &e); s = e; }
    float scl = ldexpf(1.0f, -s);
#pragma unroll
    for (int k = 0; k < 9; k++) A[k] *= scl;

    float A2[9], A3[9];
    mm3f(A, A, A2);
    mm3f(A2, A, A3);

    const float c2 = 1.0f / 2, c3 = 1.0f / 6, c4 = 1.0f / 24, c5 = 1.0f / 120;
    const float c6 = 1.0f / 720, c7 = 1.0f / 5040, c8 = 1.0f / 40320;
    const float c9 = 1.0f / 362880, c10 = 1.0f / 3628800, c11 = 1.0f / 39916800;

    float P[9], T[9];
#pragma unroll
    for (int k = 0; k < 9; k++) P[k] = fmaf(c10, A[k], c11 * A2[k]);
    P[0] += c9; P[4] += c9; P[8] += c9;

    mm3f(P, A3, T);
#pragma unroll
    for (int k = 0; k < 9; k++) P[k] = fmaf(c7, A[k], fmaf(c8, A2[k], T[k]));
    P[0] += c6; P[4] += c6; P[8] += c6;

    mm3f(P, A3, T);
#pragma unroll
    for (int k = 0; k < 9; k++) P[k] = fmaf(c4, A[k], fmaf(c5, A2[k], T[k]));
    P[0] += c3; P[4] += c3; P[8] += c3;

    mm3f(P, A3, T);
#pragma unroll
    for (int k = 0; k < 9; k++) P[k] = fmaf(c2, A2[k], T[k] + A[k]);
    P[0] += 1.0f; P[4] += 1.0f; P[8] += 1.0f;

    for (int q = 0; q < s; q++) {
        mm3f(P, P, T);
#pragma unroll
        for (int k = 0; k < 9; k++) P[k] = T[k];
    }

    // Trust test: large ||A|| amplification, or H[2][2] small vs max|H|
    // (normalization blow-up). Negated comparisons catch NaN too.
    float mx = 0.0f;
#pragma unroll
    for (int k = 0; k < 9; k++) mx = fmaxf(mx, fabsf(P[k]));
    bool ok = (nrm <= 6.0f) && (fabsf(P[8]) >= 0.02f * mx);

    if (!ok) {
        int slot = atomicAdd(&g_count, 1);
        if (slot < MAXB) g_flag_idx[slot] = i;
    }

    float inv = 1.0f / P[8];
    float* o = out + 9 * (size_t)i;
#pragma unroll
    for (int k = 0; k < 9; k++) o[k] = P[k] * inv;
}

__global__ void __launch_bounds__(256)
pass2_f64_kernel(const float* __restrict__ lie, float* __restrict__ out) {
    int cnt = g_count;
    if (cnt > MAXB) cnt = MAXB;
    for (int t = blockIdx.x * blockDim.x + threadIdx.x; t < cnt;
         t += gridDim.x * blockDim.x) {
        int idx = g_flag_idx[t];
        expm_f64(lie, out, (long long)idx);
    }
}

extern "C" void kernel_launch(void* const* d_in, const int* in_sizes, int n_in,
                              void* d_out, int out_size) {
    const float* lie = (const float*)d_in[0];
    float* out = (float*)d_out;
    int n = in_sizes[0] / 8;
    int threads = 256;
    int blocks = (n + threads - 1) / threads;

    zero_count_kernel<<<1, 1>>>();
    pass1_f32_kernel<<<blocks, threads>>>(lie, out, n);
    pass2_f64_kernel<<<1024, 256>>>(lie, out);
}

// round 4
// speedup vs baseline: 5.7776x; 1.5911x over previous
#include <cuda_runtime.h>
#include <math.h>

// Hybrid-precision batched expm of sl(3) elements:
//   Pass 1 (fp32): scaling-and-squaring to theta=2, PS degree-11 Taylor.
//     Flags untrustworthy samples (large ||A|| or near-zero H[2][2]) into a
//     compacted index list via warp-aggregated atomics.
//   Pass 2 (fp64): recomputes only the flagged samples (theta=1).

#define MAXB (1 << 20)
__device__ int g_count;
__device__ int g_flag_idx[MAXB];

// ---------------- fp64 path ----------------
__device__ __forceinline__ void mm3d(const double* __restrict__ a,
                                     const double* __restrict__ b,
                                     double* __restrict__ c) {
#pragma unroll
    for (int i = 0; i < 3; i++)
#pragma unroll
        for (int j = 0; j < 3; j++) {
            double s = a[i * 3] * b[j];
            s = fma(a[i * 3 + 1], b[3 + j], s);
            s = fma(a[i * 3 + 2], b[6 + j], s);
            c[i * 3 + j] = s;
        }
}

__device__ void expm_f64(const float* __restrict__ lie, float* __restrict__ out,
                         long long i) {
    const float4* vp = reinterpret_cast<const float4*>(lie) + 2 * i;
    float4 v0 = vp[0];
    float4 v1 = vp[1];

    double x = (double)v0.x, y = (double)v0.y, r = (double)v0.z, sc = (double)v0.w;
    double st = (double)v1.x, sh = (double)v1.y, kx = (double)v1.z, ky = (double)v1.w;

    double A[9];
    A[0] = sc + st;  A[1] = sh - r;   A[2] = x;
    A[3] = sh + r;   A[4] = sc - st;  A[5] = y;
    A[6] = kx;       A[7] = ky;       A[8] = -2.0 * sc;

    double r0 = fabs(A[0]) + fabs(A[1]) + fabs(A[2]);
    double r1 = fabs(A[3]) + fabs(A[4]) + fabs(A[5]);
    double r2 = fabs(A[6]) + fabs(A[7]) + fabs(A[8]);
    double nrm = fmax(r0, fmax(r1, r2));

    int s = 0;
    if (nrm > 1.0) { int e; frexp(nrm, &e); s = e; }
    double scl = ldexp(1.0, -s);
#pragma unroll
    for (int k = 0; k < 9; k++) A[k] *= scl;

    double A2[9], A3[9];
    mm3d(A, A, A2);
    mm3d(A2, A, A3);

    const double c2 = 1.0 / 2, c3 = 1.0 / 6, c4 = 1.0 / 24, c5 = 1.0 / 120;
    const double c6 = 1.0 / 720, c7 = 1.0 / 5040, c8 = 1.0 / 40320;
    const double c9 = 1.0 / 362880, c10 = 1.0 / 3628800, c11 = 1.0 / 39916800;

    double P[9], T[9];
#pragma unroll
    for (int k = 0; k < 9; k++) P[k] = fma(c10, A[k], c11 * A2[k]);
    P[0] += c9; P[4] += c9; P[8] += c9;

    mm3d(P, A3, T);
#pragma unroll
    for (int k = 0; k < 9; k++) P[k] = fma(c7, A[k], fma(c8, A2[k], T[k]));
    P[0] += c6; P[4] += c6; P[8] += c6;

    mm3d(P, A3, T);
#pragma unroll
    for (int k = 0; k < 9; k++) P[k] = fma(c4, A[k], fma(c5, A2[k], T[k]));
    P[0] += c3; P[4] += c3; P[8] += c3;

    mm3d(P, A3, T);
#pragma unroll
    for (int k = 0; k < 9; k++) P[k] = fma(c2, A2[k], T[k] + A[k]);
    P[0] += 1.0; P[4] += 1.0; P[8] += 1.0;

    for (int q = 0; q < s; q++) {
        mm3d(P, P, T);
#pragma unroll
        for (int k = 0; k < 9; k++) P[k] = T[k];
    }

    double inv = 1.0 / P[8];
    float* o = out + 9 * i;
#pragma unroll
    for (int k = 0; k < 9; k++) o[k] = (float)(P[k] * inv);
}

// ---------------- fp32 path ----------------
__device__ __forceinline__ void mm3f(const float* __restrict__ a,
                                     const float* __restrict__ b,
                                     float* __restrict__ c) {
#pragma unroll
    for (int i = 0; i < 3; i++)
#pragma unroll
        for (int j = 0; j < 3; j++) {
            float s = a[i * 3] * b[j];
            s = fmaf(a[i * 3 + 1], b[3 + j], s);
            s = fmaf(a[i * 3 + 2], b[6 + j], s);
            c[i * 3 + j] = s;
        }
}

__global__ void zero_count_kernel() { g_count = 0; }

__global__ void __launch_bounds__(256)
pass1_f32_kernel(const float* __restrict__ lie, float* __restrict__ out, int n) {
    int i = blockIdx.x * blockDim.x + threadIdx.x;
    bool valid = (i < n);

    float4 v0 = make_float4(0.f, 0.f, 0.f, 0.f);
    float4 v1 = make_float4(0.f, 0.f, 0.f, 0.f);
    if (valid) {
        const float4* vp = reinterpret_cast<const float4*>(lie) + 2 * (size_t)i;
        v0 = vp[0];
        v1 = vp[1];
    }

    float x = v0.x, y = v0.y, r = v0.z, sc = v0.w;
    float st = v1.x, sh = v1.y, kx = v1.z, ky = v1.w;

    float A[9];
    A[0] = sc + st;  A[1] = sh - r;   A[2] = x;
    A[3] = sh + r;   A[4] = sc - st;  A[5] = y;
    A[6] = kx;       A[7] = ky;       A[8] = -2.0f * sc;

    float r0 = fabsf(A[0]) + fabsf(A[1]) + fabsf(A[2]);
    float r1 = fabsf(A[3]) + fabsf(A[4]) + fabsf(A[5]);
    float r2 = fabsf(A[6]) + fabsf(A[7]) + fabsf(A[8]);
    float nrm = fmaxf(r0, fmaxf(r1, r2));

    // Scale so that ||A||/2^s <= 2 (theta = 2): saves one squaring vs theta=1.
    int s = 0;
    if (nrm > 2.0f) { int e; frexpf(nrm, &e); s = e - 1; }
    float scl = ldexpf(1.0f, -s);
#pragma unroll
    for (int k = 0; k < 9; k++) A[k] *= scl;

    float A2[9], A3[9];
    mm3f(A, A, A2);
    mm3f(A2, A, A3);

    const float c2 = 1.0f / 2, c3 = 1.0f / 6, c4 = 1.0f / 24, c5 = 1.0f / 120;
    const float c6 = 1.0f / 720, c7 = 1.0f / 5040, c8 = 1.0f / 40320;
    const float c9 = 1.0f / 362880, c10 = 1.0f / 3628800, c11 = 1.0f / 39916800;

    float P[9], T[9];
#pragma unroll
    for (int k = 0; k < 9; k++) P[k] = fmaf(c10, A[k], c11 * A2[k]);
    P[0] += c9; P[4] += c9; P[8] += c9;

    mm3f(P, A3, T);
#pragma unroll
    for (int k = 0; k < 9; k++) P[k] = fmaf(c7, A[k], fmaf(c8, A2[k], T[k]));
    P[0] += c6; P[4] += c6; P[8] += c6;

    mm3f(P, A3, T);
#pragma unroll
    for (int k = 0; k < 9; k++) P[k] = fmaf(c4, A[k], fmaf(c5, A2[k], T[k]));
    P[0] += c3; P[4] += c3; P[8] += c3;

    mm3f(P, A3, T);
#pragma unroll
    for (int k = 0; k < 9; k++) P[k] = fmaf(c2, A2[k], T[k] + A[k]);
    P[0] += 1.0f; P[4] += 1.0f; P[8] += 1.0f;

    for (int q = 0; q < s; q++) {
        mm3f(P, P, T);
#pragma unroll
        for (int k = 0; k < 9; k++) P[k] = T[k];
    }

    // Trust test (negated comparisons catch NaN):
    //   nrm <= 14  : squaring amplification bounded (s <= 3)
    //   |H22| >= 0.01*max|H| : normalization blow-up bounded (R <= 100)
    float mx = 0.0f;
#pragma unroll
    for (int k = 0; k < 9; k++) mx = fmaxf(mx, fabsf(P[k]));
    bool flag = valid && !((nrm <= 14.0f) && (fabsf(P[8]) >= 0.01f * mx));

    // Warp-aggregated compaction: one atomic per warp.
    unsigned ballot = __ballot_sync(0xFFFFFFFFu, flag);
    if (ballot) {
        int lane = threadIdx.x & 31;
        int leader = __ffs(ballot) - 1;
        int base = 0;
        if (lane == leader)
            base = atomicAdd(&g_count, __popc(ballot));
        base = __shfl_sync(0xFFFFFFFFu, base, leader);
        if (flag) {
            int slot = base + __popc(ballot & ((1u << lane) - 1u));
            if (slot < MAXB) g_flag_idx[slot] = i;
        }
    }

    if (valid) {
        float inv = 1.0f / P[8];
        float* o = out + 9 * (size_t)i;
#pragma unroll
        for (int k = 0; k < 9; k++) o[k] = P[k] * inv;
    }
}

__global__ void __launch_bounds__(256)
pass2_f64_kernel(const float* __restrict__ lie, float* __restrict__ out) {
    int cnt = g_count;
    if (cnt > MAXB) cnt = MAXB;
    for (int t = blockIdx.x * blockDim.x + threadIdx.x; t < cnt;
         t += gridDim.x * blockDim.x) {
        int idx = g_flag_idx[t];
        expm_f64(lie, out, (long long)idx);
    }
}

extern "C" void kernel_launch(void* const* d_in, const int* in_sizes, int n_in,
                              void* d_out, int out_size) {
    const float* lie = (const float*)d_in[0];
    float* out = (float*)d_out;
    int n = in_sizes[0] / 8;
    int threads = 256;
    int blocks = (n + threads - 1) / threads;

    zero_count_kernel<<<1, 1>>>();
    pass1_f32_kernel<<<blocks, threads>>>(lie, out, n);
    pass2_f64_kernel<<<1024, 256>>>(lie, out);
}

// round 5
// speedup vs baseline: 7.6105x; 1.3172x over previous
#include <cuda_runtime.h>
#include <math.h>

// Hybrid-precision batched expm of sl(3) elements:
//   Pass 1 (fp32): scaling-and-squaring to theta=2, PS degree-11 Taylor.
//     Flags samples whose combined amplification 2^s * mx/|H22| exceeds TAU
//     (cancellation x squaring growth) into a compacted list.
//   Pass 2 (fp64): recomputes only the flagged samples (theta=1).

#define MAXB (1 << 20)
#define TAU 1000.0f
__device__ int g_count;
__device__ int g_flag_idx[MAXB];

// ---------------- fp64 path ----------------
__device__ __forceinline__ void mm3d(const double* __restrict__ a,
                                     const double* __restrict__ b,
                                     double* __restrict__ c) {
#pragma unroll
    for (int i = 0; i < 3; i++)
#pragma unroll
        for (int j = 0; j < 3; j++) {
            double s = a[i * 3] * b[j];
            s = fma(a[i * 3 + 1], b[3 + j], s);
            s = fma(a[i * 3 + 2], b[6 + j], s);
            c[i * 3 + j] = s;
        }
}

__device__ void expm_f64(const float* __restrict__ lie, float* __restrict__ out,
                         long long i) {
    const float4* vp = reinterpret_cast<const float4*>(lie) + 2 * i;
    float4 v0 = vp[0];
    float4 v1 = vp[1];

    double x = (double)v0.x, y = (double)v0.y, r = (double)v0.z, sc = (double)v0.w;
    double st = (double)v1.x, sh = (double)v1.y, kx = (double)v1.z, ky = (double)v1.w;

    double A[9];
    A[0] = sc + st;  A[1] = sh - r;   A[2] = x;
    A[3] = sh + r;   A[4] = sc - st;  A[5] = y;
    A[6] = kx;       A[7] = ky;       A[8] = -2.0 * sc;

    double r0 = fabs(A[0]) + fabs(A[1]) + fabs(A[2]);
    double r1 = fabs(A[3]) + fabs(A[4]) + fabs(A[5]);
    double r2 = fabs(A[6]) + fabs(A[7]) + fabs(A[8]);
    double nrm = fmax(r0, fmax(r1, r2));

    int s = 0;
    if (nrm > 1.0) { int e; frexp(nrm, &e); s = e; }
    double scl = ldexp(1.0, -s);
#pragma unroll
    for (int k = 0; k < 9; k++) A[k] *= scl;

    double A2[9], A3[9];
    mm3d(A, A, A2);
    mm3d(A2, A, A3);

    const double c2 = 1.0 / 2, c3 = 1.0 / 6, c4 = 1.0 / 24, c5 = 1.0 / 120;
    const double c6 = 1.0 / 720, c7 = 1.0 / 5040, c8 = 1.0 / 40320;
    const double c9 = 1.0 / 362880, c10 = 1.0 / 3628800, c11 = 1.0 / 39916800;

    double P[9], T[9];
#pragma unroll
    for (int k = 0; k < 9; k++) P[k] = fma(c10, A[k], c11 * A2[k]);
    P[0] += c9; P[4] += c9; P[8] += c9;

    mm3d(P, A3, T);
#pragma unroll
    for (int k = 0; k < 9; k++) P[k] = fma(c7, A[k], fma(c8, A2[k], T[k]));
    P[0] += c6; P[4] += c6; P[8] += c6;

    mm3d(P, A3, T);
#pragma unroll
    for (int k = 0; k < 9; k++) P[k] = fma(c4, A[k], fma(c5, A2[k], T[k]));
    P[0] += c3; P[4] += c3; P[8] += c3;

    mm3d(P, A3, T);
#pragma unroll
    for (int k = 0; k < 9; k++) P[k] = fma(c2, A2[k], T[k] + A[k]);
    P[0] += 1.0; P[4] += 1.0; P[8] += 1.0;

    for (int q = 0; q < s; q++) {
        mm3d(P, P, T);
#pragma unroll
        for (int k = 0; k < 9; k++) P[k] = T[k];
    }

    double inv = 1.0 / P[8];
    float* o = out + 9 * i;
#pragma unroll
    for (int k = 0; k < 9; k++) o[k] = (float)(P[k] * inv);
}

// ---------------- fp32 path ----------------
__device__ __forceinline__ void mm3f(const float* __restrict__ a,
                                     const float* __restrict__ b,
                                     float* __restrict__ c) {
#pragma unroll
    for (int i = 0; i < 3; i++)
#pragma unroll
        for (int j = 0; j < 3; j++) {
            float s = a[i * 3] * b[j];
            s = fmaf(a[i * 3 + 1], b[3 + j], s);
            s = fmaf(a[i * 3 + 2], b[6 + j], s);
            c[i * 3 + j] = s;
        }
}

__global__ void zero_count_kernel() { g_count = 0; }

__global__ void __launch_bounds__(256)
pass1_f32_kernel(const float* __restrict__ lie, float* __restrict__ out, int n) {
    int i = blockIdx.x * blockDim.x + threadIdx.x;
    bool valid = (i < n);

    float4 v0 = make_float4(0.f, 0.f, 0.f, 0.f);
    float4 v1 = make_float4(0.f, 0.f, 0.f, 0.f);
    if (valid) {
        const float4* vp = reinterpret_cast<const float4*>(lie) + 2 * (size_t)i;
        v0 = vp[0];
        v1 = vp[1];
    }

    float x = v0.x, y = v0.y, r = v0.z, sc = v0.w;
    float st = v1.x, sh = v1.y, kx = v1.z, ky = v1.w;

    float A[9];
    A[0] = sc + st;  A[1] = sh - r;   A[2] = x;
    A[3] = sh + r;   A[4] = sc - st;  A[5] = y;
    A[6] = kx;       A[7] = ky;       A[8] = -2.0f * sc;

    float r0 = fabsf(A[0]) + fabsf(A[1]) + fabsf(A[2]);
    float r1 = fabsf(A[3]) + fabsf(A[4]) + fabsf(A[5]);
    float r2 = fabsf(A[6]) + fabsf(A[7]) + fabsf(A[8]);
    float nrm = fmaxf(r0, fmaxf(r1, r2));

    // Scale so that ||A||/2^s <= 2 (theta = 2).
    int s = 0;
    if (nrm > 2.0f) { int e; frexpf(nrm, &e); s = e - 1; }
    float scl = ldexpf(1.0f, -s);
#pragma unroll
    for (int k = 0; k < 9; k++) A[k] *= scl;

    float A2[9], A3[9];
    mm3f(A, A, A2);
    mm3f(A2, A, A3);

    const float c2 = 1.0f / 2, c3 = 1.0f / 6, c4 = 1.0f / 24, c5 = 1.0f / 120;
    const float c6 = 1.0f / 720, c7 = 1.0f / 5040, c8 = 1.0f / 40320;
    const float c9 = 1.0f / 362880, c10 = 1.0f / 3628800, c11 = 1.0f / 39916800;

    float P[9], T[9];
#pragma unroll
    for (int k = 0; k < 9; k++) P[k] = fmaf(c10, A[k], c11 * A2[k]);
    P[0] += c9; P[4] += c9; P[8] += c9;

    mm3f(P, A3, T);
#pragma unroll
    for (int k = 0; k < 9; k++) P[k] = fmaf(c7, A[k], fmaf(c8, A2[k], T[k]));
    P[0] += c6; P[4] += c6; P[8] += c6;

    mm3f(P, A3, T);
#pragma unroll
    for (int k = 0; k < 9; k++) P[k] = fmaf(c4, A[k], fmaf(c5, A2[k], T[k]));
    P[0] += c3; P[4] += c3; P[8] += c3;

    mm3f(P, A3, T);
#pragma unroll
    for (int k = 0; k < 9; k++) P[k] = fmaf(c2, A2[k], T[k] + A[k]);
    P[0] += 1.0f; P[4] += 1.0f; P[8] += 1.0f;

    for (int q = 0; q < s; q++) {
        mm3f(P, P, T);
#pragma unroll
        for (int k = 0; k < 9; k++) P[k] = T[k];
    }

    // Trust test: combined amplification = squaring growth x H22 cancellation.
    // Per-sample fp32 rel err ~ eps32 * amp; TAU=1000 -> ~6e-5, far under 1e-3.
    // Negated comparison catches NaN/Inf.
    float mx = 0.0f;
#pragma unroll
    for (int k = 0; k < 9; k++) mx = fmaxf(mx, fabsf(P[k]));
    float amp = ldexpf(mx, s);  // 2^s * mx
    bool flag = valid && !((nrm <= 24.0f) && (amp <= TAU * fabsf(P[8])));

    // Warp-aggregated compaction: one atomic per warp.
    unsigned ballot = __ballot_sync(0xFFFFFFFFu, flag);
    if (ballot) {
        int lane = threadIdx.x & 31;
        int leader = __ffs(ballot) - 1;
        int base = 0;
        if (lane == leader)
            base = atomicAdd(&g_count, __popc(ballot));
        base = __shfl_sync(0xFFFFFFFFu, base, leader);
        if (flag) {
            int slot = base + __popc(ballot & ((1u << lane) - 1u));
            if (slot < MAXB) g_flag_idx[slot] = i;
        }
    }

    if (valid) {
        float inv = 1.0f / P[8];
        float* o = out + 9 * (size_t)i;
#pragma unroll
        for (int k = 0; k < 9; k++) o[k] = P[k] * inv;
    }
}

__global__ void __launch_bounds__(256)
pass2_f64_kernel(const float* __restrict__ lie, float* __restrict__ out) {
    int cnt = g_count;
    if (cnt > MAXB) cnt = MAXB;
    for (int t = blockIdx.x * blockDim.x + threadIdx.x; t < cnt;
         t += gridDim.x * blockDim.x) {
        int idx = g_flag_idx[t];
        expm_f64(lie, out, (long long)idx);
    }
}

extern "C" void kernel_launch(void* const* d_in, const int* in_sizes, int n_in,
                              void* d_out, int out_size) {
    const float* lie = (const float*)d_in[0];
    float* out = (float*)d_out;
    int n = in_sizes[0] / 8;
    int threads = 256;
    int blocks = (n + threads - 1) / threads;

    zero_count_kernel<<<1, 1>>>();
    pass1_f32_kernel<<<blocks, threads>>>(lie, out, n);
    pass2_f64_kernel<<<1024, 256>>>(lie, out);
}

// round 6
// speedup vs baseline: 12.1212x; 1.5927x over previous
#include <cuda_runtime.h>
#include <math.h>

// Hybrid-precision batched expm of sl(3) elements:
//   Pass 1 (fp32): FIXED scaling s=3 (A/8), PS degree-11 Taylor, 3 unconditional
//     squarings (straight-line, no divergence). Flags samples with nrm > 16 or
//     combined amplification 8*mx/|H22| > TAU via warp-aggregated atomics.
//     Output staged through smem for coalesced stores.
//   Pass 2 (fp64): recomputes only the flagged samples (adaptive s, theta=1).

#define MAXB (1 << 20)
#define TAU 4000.0f
__device__ int g_count;
__device__ int g_flag_idx[MAXB];

// ---------------- fp64 rescue path ----------------
__device__ __forceinline__ void mm3d(const double* __restrict__ a,
                                     const double* __restrict__ b,
                                     double* __restrict__ c) {
#pragma unroll
    for (int i = 0; i < 3; i++)
#pragma unroll
        for (int j = 0; j < 3; j++) {
            double s = a[i * 3] * b[j];
            s = fma(a[i * 3 + 1], b[3 + j], s);
            s = fma(a[i * 3 + 2], b[6 + j], s);
            c[i * 3 + j] = s;
        }
}

__device__ void expm_f64(const float* __restrict__ lie, float* __restrict__ out,
                         long long i) {
    const float4* vp = reinterpret_cast<const float4*>(lie) + 2 * i;
    float4 v0 = vp[0];
    float4 v1 = vp[1];

    double x = (double)v0.x, y = (double)v0.y, r = (double)v0.z, sc = (double)v0.w;
    double st = (double)v1.x, sh = (double)v1.y, kx = (double)v1.z, ky = (double)v1.w;

    double A[9];
    A[0] = sc + st;  A[1] = sh - r;   A[2] = x;
    A[3] = sh + r;   A[4] = sc - st;  A[5] = y;
    A[6] = kx;       A[7] = ky;       A[8] = -2.0 * sc;

    double r0 = fabs(A[0]) + fabs(A[1]) + fabs(A[2]);
    double r1 = fabs(A[3]) + fabs(A[4]) + fabs(A[5]);
    double r2 = fabs(A[6]) + fabs(A[7]) + fabs(A[8]);
    double nrm = fmax(r0, fmax(r1, r2));

    int s = 0;
    if (nrm > 1.0) { int e; frexp(nrm, &e); s = e; }
    double scl = ldexp(1.0, -s);
#pragma unroll
    for (int k = 0; k < 9; k++) A[k] *= scl;

    double A2[9], A3[9];
    mm3d(A, A, A2);
    mm3d(A2, A, A3);

    const double c2 = 1.0 / 2, c3 = 1.0 / 6, c4 = 1.0 / 24, c5 = 1.0 / 120;
    const double c6 = 1.0 / 720, c7 = 1.0 / 5040, c8 = 1.0 / 40320;
    const double c9 = 1.0 / 362880, c10 = 1.0 / 3628800, c11 = 1.0 / 39916800;

    double P[9], T[9];
#pragma unroll
    for (int k = 0; k < 9; k++) P[k] = fma(c10, A[k], c11 * A2[k]);
    P[0] += c9; P[4] += c9; P[8] += c9;

    mm3d(P, A3, T);
#pragma unroll
    for (int k = 0; k < 9; k++) P[k] = fma(c7, A[k], fma(c8, A2[k], T[k]));
    P[0] += c6; P[4] += c6; P[8] += c6;

    mm3d(P, A3, T);
#pragma unroll
    for (int k = 0; k < 9; k++) P[k] = fma(c4, A[k], fma(c5, A2[k], T[k]));
    P[0] += c3; P[4] += c3; P[8] += c3;

    mm3d(P, A3, T);
#pragma unroll
    for (int k = 0; k < 9; k++) P[k] = fma(c2, A2[k], T[k] + A[k]);
    P[0] += 1.0; P[4] += 1.0; P[8] += 1.0;

    for (int q = 0; q < s; q++) {
        mm3d(P, P, T);
#pragma unroll
        for (int k = 0; k < 9; k++) P[k] = T[k];
    }

    double inv = 1.0 / P[8];
    float* o = out + 9 * i;
#pragma unroll
    for (int k = 0; k < 9; k++) o[k] = (float)(P[k] * inv);
}

// ---------------- fp32 fast path ----------------
__device__ __forceinline__ void mm3f(const float* __restrict__ a,
                                     const float* __restrict__ b,
                                     float* __restrict__ c) {
#pragma unroll
    for (int i = 0; i < 3; i++)
#pragma unroll
        for (int j = 0; j < 3; j++) {
            float s = a[i * 3] * b[j];
            s = fmaf(a[i * 3 + 1], b[3 + j], s);
            s = fmaf(a[i * 3 + 2], b[6 + j], s);
            c[i * 3 + j] = s;
        }
}

__global__ void zero_count_kernel() { g_count = 0; }

__global__ void __launch_bounds__(256)
pass1_f32_kernel(const float* __restrict__ lie, float* __restrict__ out, int n) {
    __shared__ float stage[256 * 9];

    int i = blockIdx.x * blockDim.x + threadIdx.x;
    int lane = threadIdx.x & 31;
    int warp = threadIdx.x >> 5;
    bool valid = (i < n);

    float4 v0 = make_float4(0.f, 0.f, 0.f, 0.f);
    float4 v1 = make_float4(0.f, 0.f, 0.f, 0.f);
    if (valid) {
        const float4* vp = reinterpret_cast<const float4*>(lie) + 2 * (size_t)i;
        v0 = vp[0];
        v1 = vp[1];
    }

    float x = v0.x, y = v0.y, r = v0.z, sc = v0.w;
    float st = v1.x, sh = v1.y, kx = v1.z, ky = v1.w;

    // A scaled by fixed 1/8 (s = 3): trusted domain nrm <= 16 => scaled <= 2.
    const float SCL = 0.125f;
    float A[9];
    A[0] = (sc + st) * SCL;  A[1] = (sh - r) * SCL;   A[2] = x * SCL;
    A[3] = (sh + r) * SCL;   A[4] = (sc - st) * SCL;  A[5] = y * SCL;
    A[6] = kx * SCL;         A[7] = ky * SCL;         A[8] = -2.0f * sc * SCL;

    // inf-norm of the SCALED matrix (trusted iff <= 2.0)
    float r0 = fabsf(A[0]) + fabsf(A[1]) + fabsf(A[2]);
    float r1 = fabsf(A[3]) + fabsf(A[4]) + fabsf(A[5]);
    float r2 = fabsf(A[6]) + fabsf(A[7]) + fabsf(A[8]);
    float snrm = fmaxf(r0, fmaxf(r1, r2));

    float A2[9], A3[9];
    mm3f(A, A, A2);
    mm3f(A2, A, A3);

    const float c2 = 1.0f / 2, c3 = 1.0f / 6, c4 = 1.0f / 24, c5 = 1.0f / 120;
    const float c6 = 1.0f / 720, c7 = 1.0f / 5040, c8 = 1.0f / 40320;
    const float c9 = 1.0f / 362880, c10 = 1.0f / 3628800, c11 = 1.0f / 39916800;

    float P[9], T[9];
#pragma unroll
    for (int k = 0; k < 9; k++) P[k] = fmaf(c10, A[k], c11 * A2[k]);
    P[0] += c9; P[4] += c9; P[8] += c9;

    mm3f(P, A3, T);
#pragma unroll
    for (int k = 0; k < 9; k++) P[k] = fmaf(c7, A[k], fmaf(c8, A2[k], T[k]));
    P[0] += c6; P[4] += c6; P[8] += c6;

    mm3f(P, A3, T);
#pragma unroll
    for (int k = 0; k < 9; k++) P[k] = fmaf(c4, A[k], fmaf(c5, A2[k], T[k]));
    P[0] += c3; P[4] += c3; P[8] += c3;

    mm3f(P, A3, T);
#pragma unroll
    for (int k = 0; k < 9; k++) P[k] = fmaf(c2, A2[k], T[k] + A[k]);
    P[0] += 1.0f; P[4] += 1.0f; P[8] += 1.0f;

    // Exactly 3 squarings, ping-pong (result lands in T).
    mm3f(P, P, T);
    mm3f(T, T, P);
    mm3f(P, P, T);

    // Trust test: combined amplification = 2^3 * mx / |H22| <= TAU,
    // and scaled norm in the degree-11 Taylor's domain. Negated comparison
    // catches NaN/Inf.
    float mx = 0.0f;
#pragma unroll
    for (int k = 0; k < 9; k++) mx = fmaxf(mx, fabsf(T[k]));
    bool flag = valid && !((snrm <= 2.0f) && (8.0f * mx <= TAU * fabsf(T[8])));

    // Warp-aggregated compaction: one atomic per warp.
    unsigned ballot = __ballot_sync(0xFFFFFFFFu, flag);
    if (ballot) {
        int leader = __ffs(ballot) - 1;
        int base = 0;
        if (lane == leader)
            base = atomicAdd(&g_count, __popc(ballot));
        base = __shfl_sync(0xFFFFFFFFu, base, leader);
        if (flag) {
            int slot = base + __popc(ballot & ((1u << lane) - 1u));
            if (slot < MAXB) g_flag_idx[slot] = i;
        }
    }

    // Normalize and stage into smem (stride-9 words across lanes: gcd(9,32)=1
    // -> bank-conflict-free), then warp writes 288 contiguous floats coalesced.
    float inv = 1.0f / T[8];
    float* ws = stage + warp * 288;
#pragma unroll
    for (int k = 0; k < 9; k++) ws[lane * 9 + k] = T[k] * inv;
    __syncwarp();

    long long wstart = (long long)blockIdx.x * blockDim.x + warp * 32;
    int vcount = n - (int)wstart;
    if (vcount > 32) vcount = 32;
    if (vcount > 0) {
        float* o = out + 9 * wstart;
        int total = vcount * 9;
        for (int j = lane; j < total; j += 32) o[j] = ws[j];
    }
}

__global__ void __launch_bounds__(256)
pass2_f64_kernel(const float* __restrict__ lie, float* __restrict__ out) {
    int cnt = g_count;
    if (cnt > MAXB) cnt = MAXB;
    for (int t = blockIdx.x * blockDim.x + threadIdx.x; t < cnt;
         t += gridDim.x * blockDim.x) {
        int idx = g_flag_idx[t];
        expm_f64(lie, out, (long long)idx);
    }
}

extern "C" void kernel_launch(void* const* d_in, const int* in_sizes, int n_in,
                              void* d_out, int out_size) {
    const float* lie = (const float*)d_in[0];
    float* out = (float*)d_out;
    int n = in_sizes[0] / 8;
    int threads = 256;
    int blocks = (n + threads - 1) / threads;

    zero_count_kernel<<<1, 1>>>();
    pass1_f32_kernel<<<blocks, threads>>>(lie, out, n);
    pass2_f64_kernel<<<1024, 256>>>(lie, out);
}

// round 7
// speedup vs baseline: 12.7714x; 1.0536x over previous
#include <cuda_runtime.h>
#include <math.h>

// Hybrid-precision batched expm of sl(3) elements.
//   Pass 1 (fp32, PACKED f32x2): each thread computes TWO batch items using
//     Blackwell fma.rn.f32x2 packed math. Fixed scaling s=3 (A/8), PS degree-11
//     Taylor, 3 unconditional squarings. Flags untrusted samples (scaled norm
//     > 2 or amplification 8*mx/|H22| > TAU) via warp-aggregated atomics.
//     Output staged through smem for coalesced stores.
//   Pass 2 (fp64): recomputes only the flagged samples (adaptive s, theta=1).

#define MAXB (1 << 20)
#define TAU 4000.0f
__device__ int g_count;
__device__ int g_flag_idx[MAXB];

typedef unsigned long long u64;

// ---------------- packed f32x2 helpers ----------------
__device__ __forceinline__ u64 pk2(float lo, float hi) {
    u64 r;
    asm("mov.b64 %0, {%1, %2};" : "=l"(r) : "f"(lo), "f"(hi));
    return r;
}
__device__ __forceinline__ void upk2(u64 v, float& lo, float& hi) {
    asm("mov.b64 {%0, %1}, %2;" : "=f"(lo), "=f"(hi) : "l"(v));
}
__device__ __forceinline__ u64 fma2(u64 a, u64 b, u64 c) {
    u64 d;
    asm("fma.rn.f32x2 %0, %1, %2, %3;" : "=l"(d) : "l"(a), "l"(b), "l"(c));
    return d;
}
__device__ __forceinline__ u64 mul2(u64 a, u64 b) {
    u64 d;
    asm("mul.rn.f32x2 %0, %1, %2;" : "=l"(d) : "l"(a), "l"(b));
    return d;
}
__device__ __forceinline__ u64 add2(u64 a, u64 b) {
    u64 d;
    asm("add.rn.f32x2 %0, %1, %2;" : "=l"(d) : "l"(a), "l"(b));
    return d;
}

// packed 3x3 matmul: c = a*b (27 packed FMAs -> 54 scalar FLOP-pairs)
__device__ __forceinline__ void mm3p(const u64* __restrict__ a,
                                     const u64* __restrict__ b,
                                     u64* __restrict__ c) {
#pragma unroll
    for (int i = 0; i < 3; i++)
#pragma unroll
        for (int j = 0; j < 3; j++) {
            u64 s = mul2(a[i * 3], b[j]);
            s = fma2(a[i * 3 + 1], b[3 + j], s);
            s = fma2(a[i * 3 + 2], b[6 + j], s);
            c[i * 3 + j] = s;
        }
}

// ---------------- fp64 rescue path ----------------
__device__ __forceinline__ void mm3d(const double* __restrict__ a,
                                     const double* __restrict__ b,
                                     double* __restrict__ c) {
#pragma unroll
    for (int i = 0; i < 3; i++)
#pragma unroll
        for (int j = 0; j < 3; j++) {
            double s = a[i * 3] * b[j];
            s = fma(a[i * 3 + 1], b[3 + j], s);
            s = fma(a[i * 3 + 2], b[6 + j], s);
            c[i * 3 + j] = s;
        }
}

__device__ void expm_f64(const float* __restrict__ lie, float* __restrict__ out,
                         long long i) {
    const float4* vp = reinterpret_cast<const float4*>(lie) + 2 * i;
    float4 v0 = vp[0];
    float4 v1 = vp[1];

    double x = (double)v0.x, y = (double)v0.y, r = (double)v0.z, sc = (double)v0.w;
    double st = (double)v1.x, sh = (double)v1.y, kx = (double)v1.z, ky = (double)v1.w;

    double A[9];
    A[0] = sc + st;  A[1] = sh - r;   A[2] = x;
    A[3] = sh + r;   A[4] = sc - st;  A[5] = y;
    A[6] = kx;       A[7] = ky;       A[8] = -2.0 * sc;

    double r0 = fabs(A[0]) + fabs(A[1]) + fabs(A[2]);
    double r1 = fabs(A[3]) + fabs(A[4]) + fabs(A[5]);
    double r2 = fabs(A[6]) + fabs(A[7]) + fabs(A[8]);
    double nrm = fmax(r0, fmax(r1, r2));

    int s = 0;
    if (nrm > 1.0) { int e; frexp(nrm, &e); s = e; }
    double scl = ldexp(1.0, -s);
#pragma unroll
    for (int k = 0; k < 9; k++) A[k] *= scl;

    double A2[9], A3[9];
    mm3d(A, A, A2);
    mm3d(A2, A, A3);

    const double c2 = 1.0 / 2, c3 = 1.0 / 6, c4 = 1.0 / 24, c5 = 1.0 / 120;
    const double c6 = 1.0 / 720, c7 = 1.0 / 5040, c8 = 1.0 / 40320;
    const double c9 = 1.0 / 362880, c10 = 1.0 / 3628800, c11 = 1.0 / 39916800;

    double P[9], T[9];
#pragma unroll
    for (int k = 0; k < 9; k++) P[k] = fma(c10, A[k], c11 * A2[k]);
    P[0] += c9; P[4] += c9; P[8] += c9;

    mm3d(P, A3, T);
#pragma unroll
    for (int k = 0; k < 9; k++) P[k] = fma(c7, A[k], fma(c8, A2[k], T[k]));
    P[0] += c6; P[4] += c6; P[8] += c6;

    mm3d(P, A3, T);
#pragma unroll
    for (int k = 0; k < 9; k++) P[k] = fma(c4, A[k], fma(c5, A2[k], T[k]));
    P[0] += c3; P[4] += c3; P[8] += c3;

    mm3d(P, A3, T);
#pragma unroll
    for (int k = 0; k < 9; k++) P[k] = fma(c2, A2[k], T[k] + A[k]);
    P[0] += 1.0; P[4] += 1.0; P[8] += 1.0;

    for (int q = 0; q < s; q++) {
        mm3d(P, P, T);
#pragma unroll
        for (int k = 0; k < 9; k++) P[k] = T[k];
    }

    double inv = 1.0 / P[8];
    float* o = out + 9 * i;
#pragma unroll
    for (int k = 0; k < 9; k++) o[k] = (float)(P[k] * inv);
}

// ---------------- fp32 packed fast path ----------------
__global__ void __launch_bounds__(128)
pass1_f32x2_kernel(const float* __restrict__ lie, float* __restrict__ out, int n) {
    __shared__ float stage[128 * 18];

    int t = blockIdx.x * blockDim.x + threadIdx.x;
    int lane = threadIdx.x & 31;
    int warp = threadIdx.x >> 5;
    long long i0 = 2LL * t;        // item lo
    long long i1 = i0 + 1;         // item hi
    bool vlo = (i0 < n), vhi = (i1 < n);

    float4 a0 = make_float4(0.f, 0.f, 0.f, 0.f), a1 = a0, b0 = a0, b1 = a0;
    if (vlo) {
        const float4* vp = reinterpret_cast<const float4*>(lie) + 2 * i0;
        a0 = vp[0]; a1 = vp[1];
    }
    if (vhi) {
        const float4* vp = reinterpret_cast<const float4*>(lie) + 2 * i1;
        b0 = vp[0]; b1 = vp[1];
    }

    const float SCL = 0.125f;  // fixed s = 3

    // Build scaled A for both items (scalar), compute scaled inf-norms.
    float AL[9], AH[9];
    AL[0] = (a0.w + a1.x) * SCL; AL[1] = (a1.y - a0.z) * SCL; AL[2] = a0.x * SCL;
    AL[3] = (a1.y + a0.z) * SCL; AL[4] = (a0.w - a1.x) * SCL; AL[5] = a0.y * SCL;
    AL[6] = a1.z * SCL;          AL[7] = a1.w * SCL;          AL[8] = -2.0f * a0.w * SCL;

    AH[0] = (b0.w + b1.x) * SCL; AH[1] = (b1.y - b0.z) * SCL; AH[2] = b0.x * SCL;
    AH[3] = (b1.y + b0.z) * SCL; AH[4] = (b0.w - b1.x) * SCL; AH[5] = b0.y * SCL;
    AH[6] = b1.z * SCL;          AH[7] = b1.w * SCL;          AH[8] = -2.0f * b0.w * SCL;

    float nl = fmaxf(fabsf(AL[0]) + fabsf(AL[1]) + fabsf(AL[2]),
               fmaxf(fabsf(AL[3]) + fabsf(AL[4]) + fabsf(AL[5]),
                     fabsf(AL[6]) + fabsf(AL[7]) + fabsf(AL[8])));
    float nh = fmaxf(fabsf(AH[0]) + fabsf(AH[1]) + fabsf(AH[2]),
               fmaxf(fabsf(AH[3]) + fabsf(AH[4]) + fabsf(AH[5]),
                     fabsf(AH[6]) + fabsf(AH[7]) + fabsf(AH[8])));

    // Pack.
    u64 A[9];
#pragma unroll
    for (int k = 0; k < 9; k++) A[k] = pk2(AL[k], AH[k]);

    u64 A2[9], A3[9];
    mm3p(A, A, A2);
    mm3p(A2, A, A3);

    const u64 C2  = pk2(1.0f / 2, 1.0f / 2);
    const u64 C3  = pk2(1.0f / 6, 1.0f / 6);
    const u64 C4  = pk2(1.0f / 24, 1.0f / 24);
    const u64 C5  = pk2(1.0f / 120, 1.0f / 120);
    const u64 C6  = pk2(1.0f / 720, 1.0f / 720);
    const u64 C7  = pk2(1.0f / 5040, 1.0f / 5040);
    const u64 C8  = pk2(1.0f / 40320, 1.0f / 40320);
    const u64 C9  = pk2(1.0f / 362880, 1.0f / 362880);
    const u64 C10 = pk2(1.0f / 3628800, 1.0f / 3628800);
    const u64 C11 = pk2(1.0f / 39916800, 1.0f / 39916800);
    const u64 ONE = pk2(1.0f, 1.0f);

    u64 P[9], T[9];
#pragma unroll
    for (int k = 0; k < 9; k++) P[k] = fma2(C10, A[k], mul2(C11, A2[k]));
    P[0] = add2(P[0], C9); P[4] = add2(P[4], C9); P[8] = add2(P[8], C9);

    mm3p(P, A3, T);
#pragma unroll
    for (int k = 0; k < 9; k++) P[k] = fma2(C7, A[k], fma2(C8, A2[k], T[k]));
    P[0] = add2(P[0], C6); P[4] = add2(P[4], C6); P[8] = add2(P[8], C6);

    mm3p(P, A3, T);
#pragma unroll
    for (int k = 0; k < 9; k++) P[k] = fma2(C4, A[k], fma2(C5, A2[k], T[k]));
    P[0] = add2(P[0], C3); P[4] = add2(P[4], C3); P[8] = add2(P[8], C3);

    mm3p(P, A3, T);
#pragma unroll
    for (int k = 0; k < 9; k++) P[k] = fma2(C2, A2[k], add2(T[k], A[k]));
    P[0] = add2(P[0], ONE); P[4] = add2(P[4], ONE); P[8] = add2(P[8], ONE);

    // Exactly 3 squarings, ping-pong (result in T).
    mm3p(P, P, T);
    mm3p(T, T, P);
    mm3p(P, P, T);

    // Unpack result.
    float HL[9], HH[9];
#pragma unroll
    for (int k = 0; k < 9; k++) upk2(T[k], HL[k], HH[k]);

    // Trust tests (negated comparisons catch NaN/Inf).
    float mxl = 0.0f, mxh = 0.0f;
#pragma unroll
    for (int k = 0; k < 9; k++) {
        mxl = fmaxf(mxl, fabsf(HL[k]));
        mxh = fmaxf(mxh, fabsf(HH[k]));
    }
    bool flag_lo = vlo && !((nl <= 2.0f) && (8.0f * mxl <= TAU * fabsf(HL[8])));
    bool flag_hi = vhi && !((nh <= 2.0f) && (8.0f * mxh <= TAU * fabsf(HH[8])));

    // Warp-aggregated compaction, one ballot per half.
    unsigned blo = __ballot_sync(0xFFFFFFFFu, flag_lo);
    if (blo) {
        int leader = __ffs(blo) - 1;
        int base = 0;
        if (lane == leader) base = atomicAdd(&g_count, __popc(blo));
        base = __shfl_sync(0xFFFFFFFFu, base, leader);
        if (flag_lo) {
            int slot = base + __popc(blo & ((1u << lane) - 1u));
            if (slot < MAXB) g_flag_idx[slot] = (int)i0;
        }
    }
    unsigned bhi = __ballot_sync(0xFFFFFFFFu, flag_hi);
    if (bhi) {
        int leader = __ffs(bhi) - 1;
        int base = 0;
        if (lane == leader) base = atomicAdd(&g_count, __popc(bhi));
        base = __shfl_sync(0xFFFFFFFFu, base, leader);
        if (flag_hi) {
            int slot = base + __popc(bhi & ((1u << lane) - 1u));
            if (slot < MAXB) g_flag_idx[slot] = (int)i1;
        }
    }

    // Normalize + stage to smem, then coalesced warp store of 64 items.
    float invl = 1.0f / HL[8];
    float invh = 1.0f / HH[8];
    float* ws = stage + warp * 576;  // 32 lanes * 18 floats
#pragma unroll
    for (int k = 0; k < 9; k++) {
        ws[lane * 18 + k] = HL[k] * invl;
        ws[lane * 18 + 9 + k] = HH[k] * invh;
    }
    __syncwarp();

    long long wstart = 2LL * ((long long)blockIdx.x * blockDim.x + warp * 32);
    long long rem = (long long)n - wstart;
    int vcount = (rem > 64) ? 64 : (rem > 0 ? (int)rem : 0);
    if (vcount > 0) {
        float* o = out + 9 * wstart;
        int total = vcount * 9;
        for (int j = lane; j < total; j += 32) o[j] = ws[j];
    }
}

__global__ void __launch_bounds__(256)
pass2_f64_kernel(const float* __restrict__ lie, float* __restrict__ out) {
    int cnt = g_count;
    if (cnt > MAXB) cnt = MAXB;
    for (int t = blockIdx.x * blockDim.x + threadIdx.x; t < cnt;
         t += gridDim.x * blockDim.x) {
        int idx = g_flag_idx[t];
        expm_f64(lie, out, (long long)idx);
    }
}

extern "C" void kernel_launch(void* const* d_in, const int* in_sizes, int n_in,
                              void* d_out, int out_size) {
    const float* lie = (const float*)d_in[0];
    float* out = (float*)d_out;
    int n = in_sizes[0] / 8;

    void* cnt_addr = nullptr;
    cudaGetSymbolAddress(&cnt_addr, g_count);
    cudaMemsetAsync(cnt_addr, 0, sizeof(int));

    int threads = 128;
    int items_per_block = threads * 2;
    int blocks = (n + items_per_block - 1) / items_per_block;
    pass1_f32x2_kernel<<<blocks, threads>>>(lie, out, n);
    pass2_f64_kernel<<<256, 256>>>(lie, out);
}

// round 8
// speedup vs baseline: 17.9975x; 1.4092x over previous
#include <cuda_runtime.h>
#include <math.h>

// Hybrid-precision batched expm of sl(3) elements.
//   Pass 1 (fp32, PACKED f32x2): two batch items per thread via Blackwell
//     fma.rn.f32x2. Fixed scaling s=3 (A/8), PS degree-11 Taylor, 3 squarings.
//     Flags untrusted samples (scaled norm > 2 or amplification 8*mx/|H22| >
//     TAU) via warp-aggregated atomics. Smem-staged coalesced stores.
//   Pass 2 (fp64): recomputes only the flagged samples (adaptive s, theta=1).

#define MAXB (1 << 20)
#define TAU 16384.0f
__device__ int g_count;
__device__ int g_flag_idx[MAXB];

typedef unsigned long long u64;

// ---------------- packed f32x2 helpers ----------------
__device__ __forceinline__ u64 pk2(float lo, float hi) {
    u64 r;
    asm("mov.b64 %0, {%1, %2};" : "=l"(r) : "f"(lo), "f"(hi));
    return r;
}
__device__ __forceinline__ void upk2(u64 v, float& lo, float& hi) {
    asm("mov.b64 {%0, %1}, %2;" : "=f"(lo), "=f"(hi) : "l"(v));
}
__device__ __forceinline__ u64 fma2(u64 a, u64 b, u64 c) {
    u64 d;
    asm("fma.rn.f32x2 %0, %1, %2, %3;" : "=l"(d) : "l"(a), "l"(b), "l"(c));
    return d;
}
__device__ __forceinline__ u64 mul2(u64 a, u64 b) {
    u64 d;
    asm("mul.rn.f32x2 %0, %1, %2;" : "=l"(d) : "l"(a), "l"(b));
    return d;
}
__device__ __forceinline__ u64 add2(u64 a, u64 b) {
    u64 d;
    asm("add.rn.f32x2 %0, %1, %2;" : "=l"(d) : "l"(a), "l"(b));
    return d;
}

// packed 3x3 matmul: c = a*b
__device__ __forceinline__ void mm3p(const u64* __restrict__ a,
                                     const u64* __restrict__ b,
                                     u64* __restrict__ c) {
#pragma unroll
    for (int i = 0; i < 3; i++)
#pragma unroll
        for (int j = 0; j < 3; j++) {
            u64 s = mul2(a[i * 3], b[j]);
            s = fma2(a[i * 3 + 1], b[3 + j], s);
            s = fma2(a[i * 3 + 2], b[6 + j], s);
            c[i * 3 + j] = s;
        }
}

// ---------------- fp64 rescue path ----------------
__device__ __forceinline__ void mm3d(const double* __restrict__ a,
                                     const double* __restrict__ b,
                                     double* __restrict__ c) {
#pragma unroll
    for (int i = 0; i < 3; i++)
#pragma unroll
        for (int j = 0; j < 3; j++) {
            double s = a[i * 3] * b[j];
            s = fma(a[i * 3 + 1], b[3 + j], s);
            s = fma(a[i * 3 + 2], b[6 + j], s);
            c[i * 3 + j] = s;
        }
}

__device__ void expm_f64(const float* __restrict__ lie, float* __restrict__ out,
                         long long i) {
    const float4* vp = reinterpret_cast<const float4*>(lie) + 2 * i;
    float4 v0 = vp[0];
    float4 v1 = vp[1];

    double x = (double)v0.x, y = (double)v0.y, r = (double)v0.z, sc = (double)v0.w;
    double st = (double)v1.x, sh = (double)v1.y, kx = (double)v1.z, ky = (double)v1.w;

    double A[9];
    A[0] = sc + st;  A[1] = sh - r;   A[2] = x;
    A[3] = sh + r;   A[4] = sc - st;  A[5] = y;
    A[6] = kx;       A[7] = ky;       A[8] = -2.0 * sc;

    double r0 = fabs(A[0]) + fabs(A[1]) + fabs(A[2]);
    double r1 = fabs(A[3]) + fabs(A[4]) + fabs(A[5]);
    double r2 = fabs(A[6]) + fabs(A[7]) + fabs(A[8]);
    double nrm = fmax(r0, fmax(r1, r2));

    int s = 0;
    if (nrm > 1.0) { int e; frexp(nrm, &e); s = e; }
    double scl = ldexp(1.0, -s);
#pragma unroll
    for (int k = 0; k < 9; k++) A[k] *= scl;

    double A2[9], A3[9];
    mm3d(A, A, A2);
    mm3d(A2, A, A3);

    const double c2 = 1.0 / 2, c3 = 1.0 / 6, c4 = 1.0 / 24, c5 = 1.0 / 120;
    const double c6 = 1.0 / 720, c7 = 1.0 / 5040, c8 = 1.0 / 40320;
    const double c9 = 1.0 / 362880, c10 = 1.0 / 3628800, c11 = 1.0 / 39916800;

    double P[9], T[9];
#pragma unroll
    for (int k = 0; k < 9; k++) P[k] = fma(c10, A[k], c11 * A2[k]);
    P[0] += c9; P[4] += c9; P[8] += c9;

    mm3d(P, A3, T);
#pragma unroll
    for (int k = 0; k < 9; k++) P[k] = fma(c7, A[k], fma(c8, A2[k], T[k]));
    P[0] += c6; P[4] += c6; P[8] += c6;

    mm3d(P, A3, T);
#pragma unroll
    for (int k = 0; k < 9; k++) P[k] = fma(c4, A[k], fma(c5, A2[k], T[k]));
    P[0] += c3; P[4] += c3; P[8] += c3;

    mm3d(P, A3, T);
#pragma unroll
    for (int k = 0; k < 9; k++) P[k] = fma(c2, A2[k], T[k] + A[k]);
    P[0] += 1.0; P[4] += 1.0; P[8] += 1.0;

    for (int q = 0; q < s; q++) {
        mm3d(P, P, T);
#pragma unroll
        for (int k = 0; k < 9; k++) P[k] = T[k];
    }

    double inv = 1.0 / P[8];
    float* o = out + 9 * i;
#pragma unroll
    for (int k = 0; k < 9; k++) o[k] = (float)(P[k] * inv);
}

// ---------------- fp32 packed fast path ----------------
__global__ void __launch_bounds__(128)
pass1_f32x2_kernel(const float* __restrict__ lie, float* __restrict__ out, int n) {
    __shared__ float stage[128 * 18];

    int t = blockIdx.x * blockDim.x + threadIdx.x;
    int lane = threadIdx.x & 31;
    int warp = threadIdx.x >> 5;
    long long i0 = 2LL * t;
    long long i1 = i0 + 1;
    bool vlo = (i0 < n), vhi = (i1 < n);

    float4 a0 = make_float4(0.f, 0.f, 0.f, 0.f), a1 = a0, b0 = a0, b1 = a0;
    if (vlo) {
        const float4* vp = reinterpret_cast<const float4*>(lie) + 2 * i0;
        a0 = vp[0]; a1 = vp[1];
    }
    if (vhi) {
        const float4* vp = reinterpret_cast<const float4*>(lie) + 2 * i1;
        b0 = vp[0]; b1 = vp[1];
    }

    const float SCL = 0.125f;  // fixed s = 3

    float AL[9], AH[9];
    AL[0] = (a0.w + a1.x) * SCL; AL[1] = (a1.y - a0.z) * SCL; AL[2] = a0.x * SCL;
    AL[3] = (a1.y + a0.z) * SCL; AL[4] = (a0.w - a1.x) * SCL; AL[5] = a0.y * SCL;
    AL[6] = a1.z * SCL;          AL[7] = a1.w * SCL;          AL[8] = -2.0f * a0.w * SCL;

    AH[0] = (b0.w + b1.x) * SCL; AH[1] = (b1.y - b0.z) * SCL; AH[2] = b0.x * SCL;
    AH[3] = (b1.y + b0.z) * SCL; AH[4] = (b0.w - b1.x) * SCL; AH[5] = b0.y * SCL;
    AH[6] = b1.z * SCL;          AH[7] = b1.w * SCL;          AH[8] = -2.0f * b0.w * SCL;

    float nl = fmaxf(fabsf(AL[0]) + fabsf(AL[1]) + fabsf(AL[2]),
               fmaxf(fabsf(AL[3]) + fabsf(AL[4]) + fabsf(AL[5]),
                     fabsf(AL[6]) + fabsf(AL[7]) + fabsf(AL[8])));
    float nh = fmaxf(fabsf(AH[0]) + fabsf(AH[1]) + fabsf(AH[2]),
               fmaxf(fabsf(AH[3]) + fabsf(AH[4]) + fabsf(AH[5]),
                     fabsf(AH[6]) + fabsf(AH[7]) + fabsf(AH[8])));

    u64 A[9];
#pragma unroll
    for (int k = 0; k < 9; k++) A[k] = pk2(AL[k], AH[k]);

    u64 A2[9], A3[9];
    mm3p(A, A, A2);
    mm3p(A2, A, A3);

    const u64 C2  = pk2(1.0f / 2, 1.0f / 2);
    const u64 C3  = pk2(1.0f / 6, 1.0f / 6);
    const u64 C4  = pk2(1.0f / 24, 1.0f / 24);
    const u64 C5  = pk2(1.0f / 120, 1.0f / 120);
    const u64 C6  = pk2(1.0f / 720, 1.0f / 720);
    const u64 C7  = pk2(1.0f / 5040, 1.0f / 5040);
    const u64 C8  = pk2(1.0f / 40320, 1.0f / 40320);
    const u64 C9  = pk2(1.0f / 362880, 1.0f / 362880);
    const u64 C10 = pk2(1.0f / 3628800, 1.0f / 3628800);
    const u64 C11 = pk2(1.0f / 39916800, 1.0f / 39916800);
    const u64 ONE = pk2(1.0f, 1.0f);

    u64 P[9], T[9];
#pragma unroll
    for (int k = 0; k < 9; k++) P[k] = fma2(C10, A[k], mul2(C11, A2[k]));
    P[0] = add2(P[0], C9); P[4] = add2(P[4], C9); P[8] = add2(P[8], C9);

    mm3p(P, A3, T);
#pragma unroll
    for (int k = 0; k < 9; k++) P[k] = fma2(C7, A[k], fma2(C8, A2[k], T[k]));
    P[0] = add2(P[0], C6); P[4] = add2(P[4], C6); P[8] = add2(P[8], C6);

    mm3p(P, A3, T);
#pragma unroll
    for (int k = 0; k < 9; k++) P[k] = fma2(C4, A[k], fma2(C5, A2[k], T[k]));
    P[0] = add2(P[0], C3); P[4] = add2(P[4], C3); P[8] = add2(P[8], C3);

    mm3p(P, A3, T);
#pragma unroll
    for (int k = 0; k < 9; k++) P[k] = fma2(C2, A2[k], add2(T[k], A[k]));
    P[0] = add2(P[0], ONE); P[4] = add2(P[4], ONE); P[8] = add2(P[8], ONE);

    mm3p(P, P, T);
    mm3p(T, T, P);
    mm3p(P, P, T);

    float HL[9], HH[9];
#pragma unroll
    for (int k = 0; k < 9; k++) upk2(T[k], HL[k], HH[k]);

    float mxl = 0.0f, mxh = 0.0f;
#pragma unroll
    for (int k = 0; k < 9; k++) {
        mxl = fmaxf(mxl, fabsf(HL[k]));
        mxh = fmaxf(mxh, fabsf(HH[k]));
    }
    bool flag_lo = vlo && !((nl <= 2.0f) && (8.0f * mxl <= TAU * fabsf(HL[8])));
    bool flag_hi = vhi && !((nh <= 2.0f) && (8.0f * mxh <= TAU * fabsf(HH[8])));

    unsigned blo = __ballot_sync(0xFFFFFFFFu, flag_lo);
    if (blo) {
        int leader = __ffs(blo) - 1;
        int base = 0;
        if (lane == leader) base = atomicAdd(&g_count, __popc(blo));
        base = __shfl_sync(0xFFFFFFFFu, base, leader);
        if (flag_lo) {
            int slot = base + __popc(blo & ((1u << lane) - 1u));
            if (slot < MAXB) g_flag_idx[slot] = (int)i0;
        }
    }
    unsigned bhi = __ballot_sync(0xFFFFFFFFu, flag_hi);
    if (bhi) {
        int leader = __ffs(bhi) - 1;
        int base = 0;
        if (lane == leader) base = atomicAdd(&g_count, __popc(bhi));
        base = __shfl_sync(0xFFFFFFFFu, base, leader);
        if (flag_hi) {
            int slot = base + __popc(bhi & ((1u << lane) - 1u));
            if (slot < MAXB) g_flag_idx[slot] = (int)i1;
        }
    }

    float invl = 1.0f / HL[8];
    float invh = 1.0f / HH[8];
    float* ws = stage + warp * 576;
#pragma unroll
    for (int k = 0; k < 9; k++) {
        ws[lane * 18 + k] = HL[k] * invl;
        ws[lane * 18 + 9 + k] = HH[k] * invh;
    }
    __syncwarp();

    long long wstart = 2LL * ((long long)blockIdx.x * blockDim.x + warp * 32);
    long long rem = (long long)n - wstart;
    int vcount = (rem > 64) ? 64 : (rem > 0 ? (int)rem : 0);
    if (vcount > 0) {
        float* o = out + 9 * wstart;
        int total = vcount * 9;
        for (int j = lane; j < total; j += 32) o[j] = ws[j];
    }
}

__global__ void __launch_bounds__(128)
pass2_f64_kernel(const float* __restrict__ lie, float* __restrict__ out) {
    int cnt = g_count;
    if (cnt > MAXB) cnt = MAXB;
    for (int t = blockIdx.x * blockDim.x + threadIdx.x; t < cnt;
         t += gridDim.x * blockDim.x) {
        int idx = g_flag_idx[t];
        expm_f64(lie, out, (long long)idx);
    }
}

extern "C" void kernel_launch(void* const* d_in, const int* in_sizes, int n_in,
                              void* d_out, int out_size) {
    const float* lie = (const float*)d_in[0];
    float* out = (float*)d_out;
    int n = in_sizes[0] / 8;

    void* cnt_addr = nullptr;
    cudaGetSymbolAddress(&cnt_addr, g_count);
    cudaMemsetAsync(cnt_addr, 0, sizeof(int));

    int threads = 128;
    int items_per_block = threads * 2;
    int blocks = (n + items_per_block - 1) / items_per_block;
    pass1_f32x2_kernel<<<blocks, threads>>>(lie, out, n);
    pass2_f64_kernel<<<512, 128>>>(lie, out);
}

// round 9
// speedup vs baseline: 18.0718x; 1.0041x over previous
#include <cuda_runtime.h>
#include <math.h>

// Hybrid-precision batched expm of sl(3) elements.
//   Pass 1 (fp32, PACKED f32x2): two batch items per thread via Blackwell
//     fma.rn.f32x2. Fixed scaling s=3 (A/8), PS degree-11 Taylor, 3 squarings.
//     Flags untrusted samples (scaled norm > 2 or amplification 8*mx/|H22| >
//     TAU) via warp-aggregated atomics. Smem-staged coalesced stores.
//   Pass 2 (fp64): recomputes only the flagged samples (adaptive s, theta=1).

#define MAXB (1 << 20)
#define TAU 262144.0f
__device__ int g_count;
__device__ int g_flag_idx[MAXB];

typedef unsigned long long u64;

// ---------------- packed f32x2 helpers ----------------
__device__ __forceinline__ u64 pk2(float lo, float hi) {
    u64 r;
    asm("mov.b64 %0, {%1, %2};" : "=l"(r) : "f"(lo), "f"(hi));
    return r;
}
__device__ __forceinline__ void upk2(u64 v, float& lo, float& hi) {
    asm("mov.b64 {%0, %1}, %2;" : "=f"(lo), "=f"(hi) : "l"(v));
}
__device__ __forceinline__ u64 fma2(u64 a, u64 b, u64 c) {
    u64 d;
    asm("fma.rn.f32x2 %0, %1, %2, %3;" : "=l"(d) : "l"(a), "l"(b), "l"(c));
    return d;
}
__device__ __forceinline__ u64 mul2(u64 a, u64 b) {
    u64 d;
    asm("mul.rn.f32x2 %0, %1, %2;" : "=l"(d) : "l"(a), "l"(b));
    return d;
}
__device__ __forceinline__ u64 add2(u64 a, u64 b) {
    u64 d;
    asm("add.rn.f32x2 %0, %1, %2;" : "=l"(d) : "l"(a), "l"(b));
    return d;
}

// packed 3x3 matmul: c = a*b
__device__ __forceinline__ void mm3p(const u64* __restrict__ a,
                                     const u64* __restrict__ b,
                                     u64* __restrict__ c) {
#pragma unroll
    for (int i = 0; i < 3; i++)
#pragma unroll
        for (int j = 0; j < 3; j++) {
            u64 s = mul2(a[i * 3], b[j]);
            s = fma2(a[i * 3 + 1], b[3 + j], s);
            s = fma2(a[i * 3 + 2], b[6 + j], s);
            c[i * 3 + j] = s;
        }
}

// ---------------- fp64 rescue path ----------------
__device__ __forceinline__ void mm3d(const double* __restrict__ a,
                                     const double* __restrict__ b,
                                     double* __restrict__ c) {
#pragma unroll
    for (int i = 0; i < 3; i++)
#pragma unroll
        for (int j = 0; j < 3; j++) {
            double s = a[i * 3] * b[j];
            s = fma(a[i * 3 + 1], b[3 + j], s);
            s = fma(a[i * 3 + 2], b[6 + j], s);
            c[i * 3 + j] = s;
        }
}

__device__ void expm_f64(const float* __restrict__ lie, float* __restrict__ out,
                         long long i) {
    const float4* vp = reinterpret_cast<const float4*>(lie) + 2 * i;
    float4 v0 = vp[0];
    float4 v1 = vp[1];

    double x = (double)v0.x, y = (double)v0.y, r = (double)v0.z, sc = (double)v0.w;
    double st = (double)v1.x, sh = (double)v1.y, kx = (double)v1.z, ky = (double)v1.w;

    double A[9];
    A[0] = sc + st;  A[1] = sh - r;   A[2] = x;
    A[3] = sh + r;   A[4] = sc - st;  A[5] = y;
    A[6] = kx;       A[7] = ky;       A[8] = -2.0 * sc;

    double r0 = fabs(A[0]) + fabs(A[1]) + fabs(A[2]);
    double r1 = fabs(A[3]) + fabs(A[4]) + fabs(A[5]);
    double r2 = fabs(A[6]) + fabs(A[7]) + fabs(A[8]);
    double nrm = fmax(r0, fmax(r1, r2));

    int s = 0;
    if (nrm > 1.0) { int e; frexp(nrm, &e); s = e; }
    double scl = ldexp(1.0, -s);
#pragma unroll
    for (int k = 0; k < 9; k++) A[k] *= scl;

    double A2[9], A3[9];
    mm3d(A, A, A2);
    mm3d(A2, A, A3);

    const double c2 = 1.0 / 2, c3 = 1.0 / 6, c4 = 1.0 / 24, c5 = 1.0 / 120;
    const double c6 = 1.0 / 720, c7 = 1.0 / 5040, c8 = 1.0 / 40320;
    const double c9 = 1.0 / 362880, c10 = 1.0 / 3628800, c11 = 1.0 / 39916800;

    double P[9], T[9];
#pragma unroll
    for (int k = 0; k < 9; k++) P[k] = fma(c10, A[k], c11 * A2[k]);
    P[0] += c9; P[4] += c9; P[8] += c9;

    mm3d(P, A3, T);
#pragma unroll
    for (int k = 0; k < 9; k++) P[k] = fma(c7, A[k], fma(c8, A2[k], T[k]));
    P[0] += c6; P[4] += c6; P[8] += c6;

    mm3d(P, A3, T);
#pragma unroll
    for (int k = 0; k < 9; k++) P[k] = fma(c4, A[k], fma(c5, A2[k], T[k]));
    P[0] += c3; P[4] += c3; P[8] += c3;

    mm3d(P, A3, T);
#pragma unroll
    for (int k = 0; k < 9; k++) P[k] = fma(c2, A2[k], T[k] + A[k]);
    P[0] += 1.0; P[4] += 1.0; P[8] += 1.0;

    for (int q = 0; q < s; q++) {
        mm3d(P, P, T);
#pragma unroll
        for (int k = 0; k < 9; k++) P[k] = T[k];
    }

    double inv = 1.0 / P[8];
    float* o = out + 9 * i;
#pragma unroll
    for (int k = 0; k < 9; k++) o[k] = (float)(P[k] * inv);
}

// ---------------- fp32 packed fast path ----------------
__global__ void __launch_bounds__(128)
pass1_f32x2_kernel(const float* __restrict__ lie, float* __restrict__ out, int n) {
    __shared__ float stage[128 * 18];

    int t = blockIdx.x * blockDim.x + threadIdx.x;
    int lane = threadIdx.x & 31;
    int warp = threadIdx.x >> 5;
    long long i0 = 2LL * t;
    long long i1 = i0 + 1;
    bool vlo = (i0 < n), vhi = (i1 < n);

    float4 a0 = make_float4(0.f, 0.f, 0.f, 0.f), a1 = a0, b0 = a0, b1 = a0;
    if (vlo) {
        const float4* vp = reinterpret_cast<const float4*>(lie) + 2 * i0;
        a0 = vp[0]; a1 = vp[1];
    }
    if (vhi) {
        const float4* vp = reinterpret_cast<const float4*>(lie) + 2 * i1;
        b0 = vp[0]; b1 = vp[1];
    }

    const float SCL = 0.125f;  // fixed s = 3

    float AL[9], AH[9];
    AL[0] = (a0.w + a1.x) * SCL; AL[1] = (a1.y - a0.z) * SCL; AL[2] = a0.x * SCL;
    AL[3] = (a1.y + a0.z) * SCL; AL[4] = (a0.w - a1.x) * SCL; AL[5] = a0.y * SCL;
    AL[6] = a1.z * SCL;          AL[7] = a1.w * SCL;          AL[8] = -2.0f * a0.w * SCL;

    AH[0] = (b0.w + b1.x) * SCL; AH[1] = (b1.y - b0.z) * SCL; AH[2] = b0.x * SCL;
    AH[3] = (b1.y + b0.z) * SCL; AH[4] = (b0.w - b1.x) * SCL; AH[5] = b0.y * SCL;
    AH[6] = b1.z * SCL;          AH[7] = b1.w * SCL;          AH[8] = -2.0f * b0.w * SCL;

    float nl = fmaxf(fabsf(AL[0]) + fabsf(AL[1]) + fabsf(AL[2]),
               fmaxf(fabsf(AL[3]) + fabsf(AL[4]) + fabsf(AL[5]),
                     fabsf(AL[6]) + fabsf(AL[7]) + fabsf(AL[8])));
    float nh = fmaxf(fabsf(AH[0]) + fabsf(AH[1]) + fabsf(AH[2]),
               fmaxf(fabsf(AH[3]) + fabsf(AH[4]) + fabsf(AH[5]),
                     fabsf(AH[6]) + fabsf(AH[7]) + fabsf(AH[8])));

    u64 A[9];
#pragma unroll
    for (int k = 0; k < 9; k++) A[k] = pk2(AL[k], AH[k]);

    u64 A2[9], A3[9];
    mm3p(A, A, A2);
    mm3p(A2, A, A3);

    const u64 C2  = pk2(1.0f / 2, 1.0f / 2);
    const u64 C3  = pk2(1.0f / 6, 1.0f / 6);
    const u64 C4  = pk2(1.0f / 24, 1.0f / 24);
    const u64 C5  = pk2(1.0f / 120, 1.0f / 120);
    const u64 C6  = pk2(1.0f / 720, 1.0f / 720);
    const u64 C7  = pk2(1.0f / 5040, 1.0f / 5040);
    const u64 C8  = pk2(1.0f / 40320, 1.0f / 40320);
    const u64 C9  = pk2(1.0f / 362880, 1.0f / 362880);
    const u64 C10 = pk2(1.0f / 3628800, 1.0f / 3628800);
    const u64 C11 = pk2(1.0f / 39916800, 1.0f / 39916800);
    const u64 ONE = pk2(1.0f, 1.0f);

    u64 P[9], T[9];
#pragma unroll
    for (int k = 0; k < 9; k++) P[k] = fma2(C10, A[k], mul2(C11, A2[k]));
    P[0] = add2(P[0], C9); P[4] = add2(P[4], C9); P[8] = add2(P[8], C9);

    mm3p(P, A3, T);
#pragma unroll
    for (int k = 0; k < 9; k++) P[k] = fma2(C7, A[k], fma2(C8, A2[k], T[k]));
    P[0] = add2(P[0], C6); P[4] = add2(P[4], C6); P[8] = add2(P[8], C6);

    mm3p(P, A3, T);
#pragma unroll
    for (int k = 0; k < 9; k++) P[k] = fma2(C4, A[k], fma2(C5, A2[k], T[k]));
    P[0] = add2(P[0], C3); P[4] = add2(P[4], C3); P[8] = add2(P[8], C3);

    mm3p(P, A3, T);
#pragma unroll
    for (int k = 0; k < 9; k++) P[k] = fma2(C2, A2[k], add2(T[k], A[k]));
    P[0] = add2(P[0], ONE); P[4] = add2(P[4], ONE); P[8] = add2(P[8], ONE);

    mm3p(P, P, T);
    mm3p(T, T, P);
    mm3p(P, P, T);

    float HL[9], HH[9];
#pragma unroll
    for (int k = 0; k < 9; k++) upk2(T[k], HL[k], HH[k]);

    float mxl = 0.0f, mxh = 0.0f;
#pragma unroll
    for (int k = 0; k < 9; k++) {
        mxl = fmaxf(mxl, fabsf(HL[k]));
        mxh = fmaxf(mxh, fabsf(HH[k]));
    }
    bool flag_lo = vlo && !((nl <= 2.0f) && (8.0f * mxl <= TAU * fabsf(HL[8])));
    bool flag_hi = vhi && !((nh <= 2.0f) && (8.0f * mxh <= TAU * fabsf(HH[8])));

    unsigned blo = __ballot_sync(0xFFFFFFFFu, flag_lo);
    if (blo) {
        int leader = __ffs(blo) - 1;
        int base = 0;
        if (lane == leader) base = atomicAdd(&g_count, __popc(blo));
        base = __shfl_sync(0xFFFFFFFFu, base, leader);
        if (flag_lo) {
            int slot = base + __popc(blo & ((1u << lane) - 1u));
            if (slot < MAXB) g_flag_idx[slot] = (int)i0;
        }
    }
    unsigned bhi = __ballot_sync(0xFFFFFFFFu, flag_hi);
    if (bhi) {
        int leader = __ffs(bhi) - 1;
        int base = 0;
        if (lane == leader) base = atomicAdd(&g_count, __popc(bhi));
        base = __shfl_sync(0xFFFFFFFFu, base, leader);
        if (flag_hi) {
            int slot = base + __popc(bhi & ((1u << lane) - 1u));
            if (slot < MAXB) g_flag_idx[slot] = (int)i1;
        }
    }

    float invl = 1.0f / HL[8];
    float invh = 1.0f / HH[8];
    float* ws = stage + warp * 576;
#pragma unroll
    for (int k = 0; k < 9; k++) {
        ws[lane * 18 + k] = HL[k] * invl;
        ws[lane * 18 + 9 + k] = HH[k] * invh;
    }
    __syncwarp();

    long long wstart = 2LL * ((long long)blockIdx.x * blockDim.x + warp * 32);
    long long rem = (long long)n - wstart;
    int vcount = (rem > 64) ? 64 : (rem > 0 ? (int)rem : 0);
    if (vcount > 0) {
        float* o = out + 9 * wstart;
        int total = vcount * 9;
        for (int j = lane; j < total; j += 32) o[j] = ws[j];
    }
}

__global__ void __launch_bounds__(128)
pass2_f64_kernel(const float* __restrict__ lie, float* __restrict__ out) {
    int cnt = g_count;
    if (cnt > MAXB) cnt = MAXB;
    for (int t = blockIdx.x * blockDim.x + threadIdx.x; t < cnt;
         t += gridDim.x * blockDim.x) {
        int idx = g_flag_idx[t];
        expm_f64(lie, out, (long long)idx);
    }
}

extern "C" void kernel_launch(void* const* d_in, const int* in_sizes, int n_in,
                              void* d_out, int out_size) {
    const float* lie = (const float*)d_in[0];
    float* out = (float*)d_out;
    int n = in_sizes[0] / 8;

    void* cnt_addr = nullptr;
    cudaGetSymbolAddress(&cnt_addr, g_count);
    cudaMemsetAsync(cnt_addr, 0, sizeof(int));

    int threads = 128;
    int items_per_block = threads * 2;
    int blocks = (n + items_per_block - 1) / items_per_block;
    pass1_f32x2_kernel<<<blocks, threads>>>(lie, out, n);
    pass2_f64_kernel<<<512, 128>>>(lie, out);
}

// round 10
// speedup vs baseline: 22.8156x; 1.2625x over previous
#include <cuda_runtime.h>
#include <math.h>

// Hybrid-precision batched expm of sl(3) elements.
//   Pass 1 (fp32, PACKED f32x2): two batch items per thread via fma.rn.f32x2.
//     Fixed scaling s=3, PS degree-11 Taylor, 3 squarings. Flags untrusted
//     samples (scaled norm > 2 or amplification 8*mx/|H22| > TAU) via
//     warp-aggregated atomics. Smem-staged coalesced stores.
//   Pass 2 (df64 double-float on the FFMA pipe -- NO fp64 instructions):
//     recomputes flagged samples with ~2^-45 effective precision, adaptive s.

#define MAXB (1 << 20)
#define TAU 262144.0f
__device__ int g_count;
__device__ int g_flag_idx[MAXB];

typedef unsigned long long u64;

// ---------------- packed f32x2 helpers (pass 1) ----------------
__device__ __forceinline__ u64 pk2(float lo, float hi) {
    u64 r;
    asm("mov.b64 %0, {%1, %2};" : "=l"(r) : "f"(lo), "f"(hi));
    return r;
}
__device__ __forceinline__ void upk2(u64 v, float& lo, float& hi) {
    asm("mov.b64 {%0, %1}, %2;" : "=f"(lo), "=f"(hi) : "l"(v));
}
__device__ __forceinline__ u64 fma2(u64 a, u64 b, u64 c) {
    u64 d;
    asm("fma.rn.f32x2 %0, %1, %2, %3;" : "=l"(d) : "l"(a), "l"(b), "l"(c));
    return d;
}
__device__ __forceinline__ u64 mul2(u64 a, u64 b) {
    u64 d;
    asm("mul.rn.f32x2 %0, %1, %2;" : "=l"(d) : "l"(a), "l"(b));
    return d;
}
__device__ __forceinline__ u64 add2(u64 a, u64 b) {
    u64 d;
    asm("add.rn.f32x2 %0, %1, %2;" : "=l"(d) : "l"(a), "l"(b));
    return d;
}

__device__ __forceinline__ void mm3p(const u64* __restrict__ a,
                                     const u64* __restrict__ b,
                                     u64* __restrict__ c) {
#pragma unroll
    for (int i = 0; i < 3; i++)
#pragma unroll
        for (int j = 0; j < 3; j++) {
            u64 s = mul2(a[i * 3], b[j]);
            s = fma2(a[i * 3 + 1], b[3 + j], s);
            s = fma2(a[i * 3 + 2], b[6 + j], s);
            c[i * 3 + j] = s;
        }
}

// ---------------- df64 (double-float) arithmetic (pass 2) ----------------
struct df { float h, l; };

// Exact error-free transforms. two_sum has NO multiplies -> immune to fmad
// contraction; two_prod uses an explicit fmaf.
__device__ __forceinline__ df two_sum(float a, float b) {
    float s = a + b;
    float bb = s - a;
    float e = (a - (s - bb)) + (b - bb);
    df r; r.h = s; r.l = e; return r;
}
__device__ __forceinline__ df quick2(float a, float b) {  // |a| >= |b|
    float s = a + b;
    float e = b - (s - a);
    df r; r.h = s; r.l = e; return r;
}
__device__ __forceinline__ df two_prod(float a, float b) {
    float p = a * b;
    float e = fmaf(a, b, -p);
    df r; r.h = p; r.l = e; return r;
}
__device__ __forceinline__ df df_add(df a, df b) {
    df s = two_sum(a.h, b.h);
    df t = two_sum(a.l, b.l);
    s.l += t.h;
    s = quick2(s.h, s.l);
    s.l += t.l;
    return quick2(s.h, s.l);
}
__device__ __forceinline__ df df_mul(df a, df b) {
    df p = two_prod(a.h, b.h);
    p.l = fmaf(a.h, b.l, fmaf(a.l, b.h, p.l));
    return quick2(p.h, p.l);
}
__device__ __forceinline__ df df_mulf(df a, float b) {  // b exact (pow2 etc.)
    df p = two_prod(a.h, b);
    p.l = fmaf(a.l, b, p.l);
    return quick2(p.h, p.l);
}
__device__ __forceinline__ df df_neg(df a) { df r; r.h = -a.h; r.l = -a.l; return r; }

// Compile-time df64 constant from a double literal (folded by nvcc; no
// runtime fp64 ops).
#define DFC(x) df{(float)(x), (float)((x) - (double)(float)(x))}

__device__ __forceinline__ void mm3df(const df* __restrict__ a,
                                      const df* __restrict__ b,
                                      df* __restrict__ c) {
#pragma unroll
    for (int i = 0; i < 3; i++)
#pragma unroll
        for (int j = 0; j < 3; j++) {
            df s = df_mul(a[i * 3], b[j]);
            s = df_add(s, df_mul(a[i * 3 + 1], b[3 + j]));
            s = df_add(s, df_mul(a[i * 3 + 2], b[6 + j]));
            c[i * 3 + j] = s;
        }
}

__device__ void expm_df64(const float* __restrict__ lie, float* __restrict__ out,
                          long long i) {
    const float4* vp = reinterpret_cast<const float4*>(lie) + 2 * i;
    float4 v0 = vp[0];
    float4 v1 = vp[1];

    float x = v0.x, y = v0.y, r = v0.z, sc = v0.w;
    float st = v1.x, sh = v1.y, kx = v1.z, ky = v1.w;

    // A entries as EXACT df64 (sums of two fp32 via two_sum; *2 exact).
    df A[9];
    A[0] = two_sum(sc, st);   A[1] = two_sum(sh, -r);  A[2] = df{x, 0.f};
    A[3] = two_sum(sh, r);    A[4] = two_sum(sc, -st); A[5] = df{y, 0.f};
    A[6] = df{kx, 0.f};       A[7] = df{ky, 0.f};      A[8] = df{-2.0f * sc, 0.f};

    // inf-norm (fp32 heads are plenty for picking s)
    float r0 = fabsf(A[0].h) + fabsf(A[1].h) + fabsf(A[2].h);
    float r1 = fabsf(A[3].h) + fabsf(A[4].h) + fabsf(A[5].h);
    float r2 = fabsf(A[6].h) + fabsf(A[7].h) + fabsf(A[8].h);
    float nrm = fmaxf(r0, fmaxf(r1, r2));

    int s = 0;
    if (nrm > 1.0f) { int e; frexpf(nrm, &e); s = e; }
    float scl = ldexpf(1.0f, -s);  // exact power of two
#pragma unroll
    for (int k = 0; k < 9; k++) A[k] = df_mulf(A[k], scl);

    df A2[9], A3[9];
    mm3df(A, A, A2);
    mm3df(A2, A, A3);

    const df C2  = DFC(1.0 / 2.0);
    const df C3  = DFC(1.0 / 6.0);
    const df C4  = DFC(1.0 / 24.0);
    const df C5  = DFC(1.0 / 120.0);
    const df C6  = DFC(1.0 / 720.0);
    const df C7  = DFC(1.0 / 5040.0);
    const df C8  = DFC(1.0 / 40320.0);
    const df C9  = DFC(1.0 / 362880.0);
    const df C10 = DFC(1.0 / 3628800.0);
    const df C11 = DFC(1.0 / 39916800.0);
    const df ONE = df{1.0f, 0.0f};

    df P[9], T[9];
#pragma unroll
    for (int k = 0; k < 9; k++)
        P[k] = df_add(df_mul(C10, A[k]), df_mul(C11, A2[k]));
    P[0] = df_add(P[0], C9); P[4] = df_add(P[4], C9); P[8] = df_add(P[8], C9);

    mm3df(P, A3, T);
#pragma unroll
    for (int k = 0; k < 9; k++)
        P[k] = df_add(T[k], df_add(df_mul(C7, A[k]), df_mul(C8, A2[k])));
    P[0] = df_add(P[0], C6); P[4] = df_add(P[4], C6); P[8] = df_add(P[8], C6);

    mm3df(P, A3, T);
#pragma unroll
    for (int k = 0; k < 9; k++)
        P[k] = df_add(T[k], df_add(df_mul(C4, A[k]), df_mul(C5, A2[k])));
    P[0] = df_add(P[0], C3); P[4] = df_add(P[4], C3); P[8] = df_add(P[8], C3);

    mm3df(P, A3, T);
#pragma unroll
    for (int k = 0; k < 9; k++)
        P[k] = df_add(T[k], df_add(A[k], df_mul(C2, A2[k])));
    P[0] = df_add(P[0], ONE); P[4] = df_add(P[4], ONE); P[8] = df_add(P[8], ONE);

    for (int q = 0; q < s; q++) {
        mm3df(P, P, T);
#pragma unroll
        for (int k = 0; k < 9; k++) P[k] = T[k];
    }

    // df64 reciprocal of P[8]: fp32 seed + one df64 Newton step (~2^-45).
    float approx = 1.0f / P[8].h;
    df e = df_mulf(P[8], approx);               // ~= 1
    df corr = df_add(df{2.0f, 0.0f}, df_neg(e)); // 2 - P8*approx
    df rcp = df_mulf(corr, approx);

    float* o = out + 9 * i;
#pragma unroll
    for (int k = 0; k < 9; k++) {
        df q = df_mul(P[k], rcp);
        o[k] = q.h + q.l;
    }
}

// ---------------- fp32 packed fast path ----------------
__global__ void __launch_bounds__(128)
pass1_f32x2_kernel(const float* __restrict__ lie, float* __restrict__ out, int n) {
    __shared__ float stage[128 * 18];

    int t = blockIdx.x * blockDim.x + threadIdx.x;
    int lane = threadIdx.x & 31;
    int warp = threadIdx.x >> 5;
    long long i0 = 2LL * t;
    long long i1 = i0 + 1;
    bool vlo = (i0 < n), vhi = (i1 < n);

    float4 a0 = make_float4(0.f, 0.f, 0.f, 0.f), a1 = a0, b0 = a0, b1 = a0;
    if (vlo) {
        const float4* vp = reinterpret_cast<const float4*>(lie) + 2 * i0;
        a0 = vp[0]; a1 = vp[1];
    }
    if (vhi) {
        const float4* vp = reinterpret_cast<const float4*>(lie) + 2 * i1;
        b0 = vp[0]; b1 = vp[1];
    }

    const float SCL = 0.125f;  // fixed s = 3

    float AL[9], AH[9];
    AL[0] = (a0.w + a1.x) * SCL; AL[1] = (a1.y - a0.z) * SCL; AL[2] = a0.x * SCL;
    AL[3] = (a1.y + a0.z) * SCL; AL[4] = (a0.w - a1.x) * SCL; AL[5] = a0.y * SCL;
    AL[6] = a1.z * SCL;          AL[7] = a1.w * SCL;          AL[8] = -2.0f * a0.w * SCL;

    AH[0] = (b0.w + b1.x) * SCL; AH[1] = (b1.y - b0.z) * SCL; AH[2] = b0.x * SCL;
    AH[3] = (b1.y + b0.z) * SCL; AH[4] = (b0.w - b1.x) * SCL; AH[5] = b0.y * SCL;
    AH[6] = b1.z * SCL;          AH[7] = b1.w * SCL;          AH[8] = -2.0f * b0.w * SCL;

    float nl = fmaxf(fabsf(AL[0]) + fabsf(AL[1]) + fabsf(AL[2]),
               fmaxf(fabsf(AL[3]) + fabsf(AL[4]) + fabsf(AL[5]),
                     fabsf(AL[6]) + fabsf(AL[7]) + fabsf(AL[8])));
    float nh = fmaxf(fabsf(AH[0]) + fabsf(AH[1]) + fabsf(AH[2]),
               fmaxf(fabsf(AH[3]) + fabsf(AH[4]) + fabsf(AH[5]),
                     fabsf(AH[6]) + fabsf(AH[7]) + fabsf(AH[8])));

    u64 A[9];
#pragma unroll
    for (int k = 0; k < 9; k++) A[k] = pk2(AL[k], AH[k]);

    u64 A2[9], A3[9];
    mm3p(A, A, A2);
    mm3p(A2, A, A3);

    const u64 C2  = pk2(1.0f / 2, 1.0f / 2);
    const u64 C3  = pk2(1.0f / 6, 1.0f / 6);
    const u64 C4  = pk2(1.0f / 24, 1.0f / 24);
    const u64 C5  = pk2(1.0f / 120, 1.0f / 120);
    const u64 C6  = pk2(1.0f / 720, 1.0f / 720);
    const u64 C7  = pk2(1.0f / 5040, 1.0f / 5040);
    const u64 C8  = pk2(1.0f / 40320, 1.0f / 40320);
    const u64 C9  = pk2(1.0f / 362880, 1.0f / 362880);
    const u64 C10 = pk2(1.0f / 3628800, 1.0f / 3628800);
    const u64 C11 = pk2(1.0f / 39916800, 1.0f / 39916800);
    const u64 ONE = pk2(1.0f, 1.0f);

    u64 P[9], T[9];
#pragma unroll
    for (int k = 0; k < 9; k++) P[k] = fma2(C10, A[k], mul2(C11, A2[k]));
    P[0] = add2(P[0], C9); P[4] = add2(P[4], C9); P[8] = add2(P[8], C9);

    mm3p(P, A3, T);
#pragma unroll
    for (int k = 0; k < 9; k++) P[k] = fma2(C7, A[k], fma2(C8, A2[k], T[k]));
    P[0] = add2(P[0], C6); P[4] = add2(P[4], C6); P[8] = add2(P[8], C6);

    mm3p(P, A3, T);
#pragma unroll
    for (int k = 0; k < 9; k++) P[k] = fma2(C4, A[k], fma2(C5, A2[k], T[k]));
    P[0] = add2(P[0], C3); P[4] = add2(P[4], C3); P[8] = add2(P[8], C3);

    mm3p(P, A3, T);
#pragma unroll
    for (int k = 0; k < 9; k++) P[k] = fma2(C2, A2[k], add2(T[k], A[k]));
    P[0] = add2(P[0], ONE); P[4] = add2(P[4], ONE); P[8] = add2(P[8], ONE);

    mm3p(P, P, T);
    mm3p(T, T, P);
    mm3p(P, P, T);

    float HL[9], HH[9];
#pragma unroll
    for (int k = 0; k < 9; k++) upk2(T[k], HL[k], HH[k]);

    float mxl = 0.0f, mxh = 0.0f;
#pragma unroll
    for (int k = 0; k < 9; k++) {
        mxl = fmaxf(mxl, fabsf(HL[k]));
        mxh = fmaxf(mxh, fabsf(HH[k]));
    }
    bool flag_lo = vlo && !((nl <= 2.0f) && (8.0f * mxl <= TAU * fabsf(HL[8])));
    bool flag_hi = vhi && !((nh <= 2.0f) && (8.0f * mxh <= TAU * fabsf(HH[8])));

    unsigned blo = __ballot_sync(0xFFFFFFFFu, flag_lo);
    if (blo) {
        int leader = __ffs(blo) - 1;
        int base = 0;
        if (lane == leader) base = atomicAdd(&g_count, __popc(blo));
        base = __shfl_sync(0xFFFFFFFFu, base, leader);
        if (flag_lo) {
            int slot = base + __popc(blo & ((1u << lane) - 1u));
            if (slot < MAXB) g_flag_idx[slot] = (int)i0;
        }
    }
    unsigned bhi = __ballot_sync(0xFFFFFFFFu, flag_hi);
    if (bhi) {
        int leader = __ffs(bhi) - 1;
        int base = 0;
        if (lane == leader) base = atomicAdd(&g_count, __popc(bhi));
        base = __shfl_sync(0xFFFFFFFFu, base, leader);
        if (flag_hi) {
            int slot = base + __popc(bhi & ((1u << lane) - 1u));
            if (slot < MAXB) g_flag_idx[slot] = (int)i1;
        }
    }

    float invl = 1.0f / HL[8];
    float invh = 1.0f / HH[8];
    float* ws = stage + warp * 576;
#pragma unroll
    for (int k = 0; k < 9; k++) {
        ws[lane * 18 + k] = HL[k] * invl;
        ws[lane * 18 + 9 + k] = HH[k] * invh;
    }
    __syncwarp();

    long long wstart = 2LL * ((long long)blockIdx.x * blockDim.x + warp * 32);
    long long rem = (long long)n - wstart;
    int vcount = (rem > 64) ? 64 : (rem > 0 ? (int)rem : 0);
    if (vcount > 0) {
        float* o = out + 9 * wstart;
        int total = vcount * 9;
        for (int j = lane; j < total; j += 32) o[j] = ws[j];
    }
}

__global__ void __launch_bounds__(128)
pass2_df64_kernel(const float* __restrict__ lie, float* __restrict__ out) {
    int cnt = g_count;
    if (cnt > MAXB) cnt = MAXB;
    for (int t = blockIdx.x * blockDim.x + threadIdx.x; t < cnt;
         t += gridDim.x * blockDim.x) {
        int idx = g_flag_idx[t];
        expm_df64(lie, out, (long long)idx);
    }
}

extern "C" void kernel_launch(void* const* d_in, const int* in_sizes, int n_in,
                              void* d_out, int out_size) {
    const float* lie = (const float*)d_in[0];
    float* out = (float*)d_out;
    int n = in_sizes[0] / 8;

    void* cnt_addr = nullptr;
    cudaGetSymbolAddress(&cnt_addr, g_count);
    cudaMemsetAsync(cnt_addr, 0, sizeof(int));

    int threads = 128;
    int items_per_block = threads * 2;
    int blocks = (n + items_per_block - 1) / items_per_block;
    pass1_f32x2_kernel<<<blocks, threads>>>(lie, out, n);
    pass2_df64_kernel<<<512, 128>>>(lie, out);
}

// round 11
// speedup vs baseline: 26.2626x; 1.1511x over previous
#include <cuda_runtime.h>
#include <math.h>

// Hybrid-precision batched expm of sl(3) elements.
//   Pass 1 (fp32, PACKED f32x2): two batch items per thread via fma.rn.f32x2.
//     Fixed scaling s=3, PS degree-11 Taylor, 3 squarings. Flags untrusted
//     samples (scaled norm > 2 or amplification 8*mx/|H22| > TAU) via
//     warp-aggregated atomics. Smem-staged coalesced stores.
//   Pass 2 (df64 double-float on the FFMA pipe, compensated-dot matmuls):
//     recomputes flagged samples with ~2^-45 effective precision, adaptive s.

#define MAXB (1 << 20)
#define TAU 1048576.0f
__device__ int g_count;
__device__ int g_flag_idx[MAXB];

typedef unsigned long long u64;

// ---------------- packed f32x2 helpers (pass 1) ----------------
__device__ __forceinline__ u64 pk2(float lo, float hi) {
    u64 r;
    asm("mov.b64 %0, {%1, %2};" : "=l"(r) : "f"(lo), "f"(hi));
    return r;
}
__device__ __forceinline__ void upk2(u64 v, float& lo, float& hi) {
    asm("mov.b64 {%0, %1}, %2;" : "=f"(lo), "=f"(hi) : "l"(v));
}
__device__ __forceinline__ u64 fma2(u64 a, u64 b, u64 c) {
    u64 d;
    asm("fma.rn.f32x2 %0, %1, %2, %3;" : "=l"(d) : "l"(a), "l"(b), "l"(c));
    return d;
}
__device__ __forceinline__ u64 mul2(u64 a, u64 b) {
    u64 d;
    asm("mul.rn.f32x2 %0, %1, %2;" : "=l"(d) : "l"(a), "l"(b));
    return d;
}
__device__ __forceinline__ u64 add2(u64 a, u64 b) {
    u64 d;
    asm("add.rn.f32x2 %0, %1, %2;" : "=l"(d) : "l"(a), "l"(b));
    return d;
}

__device__ __forceinline__ void mm3p(const u64* __restrict__ a,
                                     const u64* __restrict__ b,
                                     u64* __restrict__ c) {
#pragma unroll
    for (int i = 0; i < 3; i++)
#pragma unroll
        for (int j = 0; j < 3; j++) {
            u64 s = mul2(a[i * 3], b[j]);
            s = fma2(a[i * 3 + 1], b[3 + j], s);
            s = fma2(a[i * 3 + 2], b[6 + j], s);
            c[i * 3 + j] = s;
        }
}

// ---------------- df64 (double-float) arithmetic (pass 2) ----------------
struct df { float h, l; };

// Error-free transforms. two_sum has NO multiplies (fmad-contraction safe);
// two_prod uses an explicit fmaf.
__device__ __forceinline__ df two_sum(float a, float b) {
    float s = a + b;
    float bb = s - a;
    float e = (a - (s - bb)) + (b - bb);
    df r; r.h = s; r.l = e; return r;
}
__device__ __forceinline__ df quick2(float a, float b) {  // |a| >= |b|
    float s = a + b;
    float e = b - (s - a);
    df r; r.h = s; r.l = e; return r;
}
// Sloppy df add: abs error ~ 2^-48 * max(|a|,|b|) -- ample for our budget.
__device__ __forceinline__ df df_add(df a, df b) {
    df s = two_sum(a.h, b.h);
    s.l += (a.l + b.l);
    return quick2(s.h, s.l);
}
__device__ __forceinline__ df df_mul(df a, df b) {
    float p = a.h * b.h;
    float e = fmaf(a.h, b.h, -p);
    e = fmaf(a.h, b.l, fmaf(a.l, b.h, e));
    return quick2(p, e);
}
// Multiply by an exact power of two: both components exact.
__device__ __forceinline__ df df_scale_pow2(df a, float p2) {
    df r; r.h = a.h * p2; r.l = a.l * p2; return r;
}
__device__ __forceinline__ df df_neg(df a) { df r; r.h = -a.h; r.l = -a.l; return r; }

// Compile-time df64 constant (folded by nvcc; no runtime fp64 ops).
#define DFC(x) df{(float)(x), (float)((x) - (double)(float)(x))}

// Compensated 3-term df dot product: c = a0*b0 + a1*b1 + a2*b2.
__device__ __forceinline__ df dot3(df a0, df b0, df a1, df b1, df a2, df b2) {
    float p1 = a0.h * b0.h;
    float e1 = fmaf(a0.h, b0.h, -p1);
    e1 = fmaf(a0.h, b0.l, fmaf(a0.l, b0.h, e1));
    float p2 = a1.h * b1.h;
    float e2 = fmaf(a1.h, b1.h, -p2);
    e2 = fmaf(a1.h, b1.l, fmaf(a1.l, b1.h, e2));
    float p3 = a2.h * b2.h;
    float e3 = fmaf(a2.h, b2.h, -p3);
    e3 = fmaf(a2.h, b2.l, fmaf(a2.l, b2.h, e3));

    df s1 = two_sum(p1, p2);
    df s2 = two_sum(s1.h, p3);
    float e = ((e1 + e2) + (e3 + s1.l)) + s2.l;
    return quick2(s2.h, e);
}

__device__ __forceinline__ void mm3df(const df* __restrict__ a,
                                      const df* __restrict__ b,
                                      df* __restrict__ c) {
#pragma unroll
    for (int i = 0; i < 3; i++)
#pragma unroll
        for (int j = 0; j < 3; j++)
            c[i * 3 + j] = dot3(a[i * 3], b[j],
                                a[i * 3 + 1], b[3 + j],
                                a[i * 3 + 2], b[6 + j]);
}

__device__ void expm_df64(const float* __restrict__ lie, float* __restrict__ out,
                          long long i) {
    const float4* vp = reinterpret_cast<const float4*>(lie) + 2 * i;
    float4 v0 = vp[0];
    float4 v1 = vp[1];

    float x = v0.x, y = v0.y, r = v0.z, sc = v0.w;
    float st = v1.x, sh = v1.y, kx = v1.z, ky = v1.w;

    // A entries as EXACT df64 (two_sum of two fp32; *2 exact).
    df A[9];
    A[0] = two_sum(sc, st);   A[1] = two_sum(sh, -r);  A[2] = df{x, 0.f};
    A[3] = two_sum(sh, r);    A[4] = two_sum(sc, -st); A[5] = df{y, 0.f};
    A[6] = df{kx, 0.f};       A[7] = df{ky, 0.f};      A[8] = df{-2.0f * sc, 0.f};

    float r0 = fabsf(A[0].h) + fabsf(A[1].h) + fabsf(A[2].h);
    float r1 = fabsf(A[3].h) + fabsf(A[4].h) + fabsf(A[5].h);
    float r2 = fabsf(A[6].h) + fabsf(A[7].h) + fabsf(A[8].h);
    float nrm = fmaxf(r0, fmaxf(r1, r2));

    int s = 0;
    if (nrm > 1.0f) { int e; frexpf(nrm, &e); s = e; }
    float scl = ldexpf(1.0f, -s);  // exact power of two
#pragma unroll
    for (int k = 0; k < 9; k++) A[k] = df_scale_pow2(A[k], scl);

    df A2[9], A3[9];
    mm3df(A, A, A2);
    mm3df(A2, A, A3);

    const df C2  = DFC(1.0 / 2.0);
    const df C3  = DFC(1.0 / 6.0);
    const df C4  = DFC(1.0 / 24.0);
    const df C5  = DFC(1.0 / 120.0);
    const df C6  = DFC(1.0 / 720.0);
    const df C7  = DFC(1.0 / 5040.0);
    const df C8  = DFC(1.0 / 40320.0);
    const df C9  = DFC(1.0 / 362880.0);
    const df C10 = DFC(1.0 / 3628800.0);
    const df C11 = DFC(1.0 / 39916800.0);
    const df ONE = df{1.0f, 0.0f};

    df P[9], T[9];
#pragma unroll
    for (int k = 0; k < 9; k++)
        P[k] = df_add(df_mul(C10, A[k]), df_mul(C11, A2[k]));
    P[0] = df_add(P[0], C9); P[4] = df_add(P[4], C9); P[8] = df_add(P[8], C9);

    mm3df(P, A3, T);
#pragma unroll
    for (int k = 0; k < 9; k++)
        P[k] = df_add(T[k], df_add(df_mul(C7, A[k]), df_mul(C8, A2[k])));
    P[0] = df_add(P[0], C6); P[4] = df_add(P[4], C6); P[8] = df_add(P[8], C6);

    mm3df(P, A3, T);
#pragma unroll
    for (int k = 0; k < 9; k++)
        P[k] = df_add(T[k], df_add(df_mul(C4, A[k]), df_mul(C5, A2[k])));
    P[0] = df_add(P[0], C3); P[4] = df_add(P[4], C3); P[8] = df_add(P[8], C3);

    mm3df(P, A3, T);
#pragma unroll
    for (int k = 0; k < 9; k++)
        P[k] = df_add(T[k], df_add(A[k], df_mul(C2, A2[k])));
    P[0] = df_add(P[0], ONE); P[4] = df_add(P[4], ONE); P[8] = df_add(P[8], ONE);

    for (int q = 0; q < s; q++) {
        mm3df(P, P, T);
#pragma unroll
        for (int k = 0; k < 9; k++) P[k] = T[k];
    }

    // df64 reciprocal of P[8]: fp32 seed + one df64 Newton step.
    float approx = 1.0f / P[8].h;
    df e = df_mul(P[8], df{approx, 0.f});
    df corr = df_add(df{2.0f, 0.0f}, df_neg(e));
    df rcp = df_mul(corr, df{approx, 0.f});

    float* o = out + 9 * i;
#pragma unroll
    for (int k = 0; k < 9; k++) {
        df q = df_mul(P[k], rcp);
        o[k] = q.h + q.l;
    }
}

// ---------------- fp32 packed fast path ----------------
__global__ void __launch_bounds__(128)
pass1_f32x2_kernel(const float* __restrict__ lie, float* __restrict__ out, int n) {
    __shared__ float stage[128 * 18];

    int t = blockIdx.x * blockDim.x + threadIdx.x;
    int lane = threadIdx.x & 31;
    int warp = threadIdx.x >> 5;
    long long i0 = 2LL * t;
    long long i1 = i0 + 1;
    bool vlo = (i0 < n), vhi = (i1 < n);

    float4 a0 = make_float4(0.f, 0.f, 0.f, 0.f), a1 = a0, b0 = a0, b1 = a0;
    if (vlo) {
        const float4* vp = reinterpret_cast<const float4*>(lie) + 2 * i0;
        a0 = vp[0]; a1 = vp[1];
    }
    if (vhi) {
        const float4* vp = reinterpret_cast<const float4*>(lie) + 2 * i1;
        b0 = vp[0]; b1 = vp[1];
    }

    const float SCL = 0.125f;  // fixed s = 3

    float AL[9], AH[9];
    AL[0] = (a0.w + a1.x) * SCL; AL[1] = (a1.y - a0.z) * SCL; AL[2] = a0.x * SCL;
    AL[3] = (a1.y + a0.z) * SCL; AL[4] = (a0.w - a1.x) * SCL; AL[5] = a0.y * SCL;
    AL[6] = a1.z * SCL;          AL[7] = a1.w * SCL;          AL[8] = -2.0f * a0.w * SCL;

    AH[0] = (b0.w + b1.x) * SCL; AH[1] = (b1.y - b0.z) * SCL; AH[2] = b0.x * SCL;
    AH[3] = (b1.y + b0.z) * SCL; AH[4] = (b0.w - b1.x) * SCL; AH[5] = b0.y * SCL;
    AH[6] = b1.z * SCL;          AH[7] = b1.w * SCL;          AH[8] = -2.0f * b0.w * SCL;

    float nl = fmaxf(fabsf(AL[0]) + fabsf(AL[1]) + fabsf(AL[2]),
               fmaxf(fabsf(AL[3]) + fabsf(AL[4]) + fabsf(AL[5]),
                     fabsf(AL[6]) + fabsf(AL[7]) + fabsf(AL[8])));
    float nh = fmaxf(fabsf(AH[0]) + fabsf(AH[1]) + fabsf(AH[2]),
               fmaxf(fabsf(AH[3]) + fabsf(AH[4]) + fabsf(AH[5]),
                     fabsf(AH[6]) + fabsf(AH[7]) + fabsf(AH[8])));

    u64 A[9];
#pragma unroll
    for (int k = 0; k < 9; k++) A[k] = pk2(AL[k], AH[k]);

    u64 A2[9], A3[9];
    mm3p(A, A, A2);
    mm3p(A2, A, A3);

    const u64 C2  = pk2(1.0f / 2, 1.0f / 2);
    const u64 C3  = pk2(1.0f / 6, 1.0f / 6);
    const u64 C4  = pk2(1.0f / 24, 1.0f / 24);
    const u64 C5  = pk2(1.0f / 120, 1.0f / 120);
    const u64 C6  = pk2(1.0f / 720, 1.0f / 720);
    const u64 C7  = pk2(1.0f / 5040, 1.0f / 5040);
    const u64 C8  = pk2(1.0f / 40320, 1.0f / 40320);
    const u64 C9  = pk2(1.0f / 362880, 1.0f / 362880);
    const u64 C10 = pk2(1.0f / 3628800, 1.0f / 3628800);
    const u64 C11 = pk2(1.0f / 39916800, 1.0f / 39916800);
    const u64 ONE = pk2(1.0f, 1.0f);

    u64 P[9], T[9];
#pragma unroll
    for (int k = 0; k < 9; k++) P[k] = fma2(C10, A[k], mul2(C11, A2[k]));
    P[0] = add2(P[0], C9); P[4] = add2(P[4], C9); P[8] = add2(P[8], C9);

    mm3p(P, A3, T);
#pragma unroll
    for (int k = 0; k < 9; k++) P[k] = fma2(C7, A[k], fma2(C8, A2[k], T[k]));
    P[0] = add2(P[0], C6); P[4] = add2(P[4], C6); P[8] = add2(P[8], C6);

    mm3p(P, A3, T);
#pragma unroll
    for (int k = 0; k < 9; k++) P[k] = fma2(C4, A[k], fma2(C5, A2[k], T[k]));
    P[0] = add2(P[0], C3); P[4] = add2(P[4], C3); P[8] = add2(P[8], C3);

    mm3p(P, A3, T);
#pragma unroll
    for (int k = 0; k < 9; k++) P[k] = fma2(C2, A2[k], add2(T[k], A[k]));
    P[0] = add2(P[0], ONE); P[4] = add2(P[4], ONE); P[8] = add2(P[8], ONE);

    mm3p(P, P, T);
    mm3p(T, T, P);
    mm3p(P, P, T);

    float HL[9], HH[9];
#pragma unroll
    for (int k = 0; k < 9; k++) upk2(T[k], HL[k], HH[k]);

    float mxl = 0.0f, mxh = 0.0f;
#pragma unroll
    for (int k = 0; k < 9; k++) {
        mxl = fmaxf(mxl, fabsf(HL[k]));
        mxh = fmaxf(mxh, fabsf(HH[k]));
    }
    bool flag_lo = vlo && !((nl <= 2.0f) && (8.0f * mxl <= TAU * fabsf(HL[8])));
    bool flag_hi = vhi && !((nh <= 2.0f) && (8.0f * mxh <= TAU * fabsf(HH[8])));

    unsigned blo = __ballot_sync(0xFFFFFFFFu, flag_lo);
    if (blo) {
        int leader = __ffs(blo) - 1;
        int base = 0;
        if (lane == leader) base = atomicAdd(&g_count, __popc(blo));
        base = __shfl_sync(0xFFFFFFFFu, base, leader);
        if (flag_lo) {
            int slot = base + __popc(blo & ((1u << lane) - 1u));
            if (slot < MAXB) g_flag_idx[slot] = (int)i0;
        }
    }
    unsigned bhi = __ballot_sync(0xFFFFFFFFu, flag_hi);
    if (bhi) {
        int leader = __ffs(bhi) - 1;
        int base = 0;
        if (lane == leader) base = atomicAdd(&g_count, __popc(bhi));
        base = __shfl_sync(0xFFFFFFFFu, base, leader);
        if (flag_hi) {
            int slot = base + __popc(bhi & ((1u << lane) - 1u));
            if (slot < MAXB) g_flag_idx[slot] = (int)i1;
        }
    }

    float invl = 1.0f / HL[8];
    float invh = 1.0f / HH[8];
    float* ws = stage + warp * 576;
#pragma unroll
    for (int k = 0; k < 9; k++) {
        ws[lane * 18 + k] = HL[k] * invl;
        ws[lane * 18 + 9 + k] = HH[k] * invh;
    }
    __syncwarp();

    long long wstart = 2LL * ((long long)blockIdx.x * blockDim.x + warp * 32);
    long long rem = (long long)n - wstart;
    int vcount = (rem > 64) ? 64 : (rem > 0 ? (int)rem : 0);
    if (vcount > 0) {
        float* o = out + 9 * wstart;
        int total = vcount * 9;
        for (int j = lane; j < total; j += 32) o[j] = ws[j];
    }
}

__global__ void __launch_bounds__(64)
pass2_df64_kernel(const float* __restrict__ lie, float* __restrict__ out) {
    int cnt = g_count;
    if (cnt > MAXB) cnt = MAXB;
    for (int t = blockIdx.x * blockDim.x + threadIdx.x; t < cnt;
         t += gridDim.x * blockDim.x) {
        int idx = g_flag_idx[t];
        expm_df64(lie, out, (long long)idx);
    }
}

extern "C" void kernel_launch(void* const* d_in, const int* in_sizes, int n_in,
                              void* d_out, int out_size) {
    const float* lie = (const float*)d_in[0];
    float* out = (float*)d_out;
    int n = in_sizes[0] / 8;

    void* cnt_addr = nullptr;
    cudaGetSymbolAddress(&cnt_addr, g_count);
    cudaMemsetAsync(cnt_addr, 0, sizeof(int));

    int threads = 128;
    int items_per_block = threads * 2;
    int blocks = (n + items_per_block - 1) / items_per_block;
    pass1_f32x2_kernel<<<blocks, threads>>>(lie, out, n);
    pass2_df64_kernel<<<1024, 64>>>(lie, out);
}

// round 12
// speedup vs baseline: 29.0106x; 1.1046x over previous
#include <cuda_runtime.h>
#include <math.h>

// Hybrid-precision batched expm of sl(3) elements.
//   Pass 1 (fp32, PACKED f32x2): two batch items per thread via fma.rn.f32x2.
//     Fixed scaling s=3, PS degree-11 Taylor, 3 squarings. Flags untrusted
//     samples via warp-aggregated atomics. Smem-staged coalesced stores.
//   Pass 2 (df64, COOPERATIVE): 3 lanes per flagged item (one matrix row per
//     lane), shuffle-based 3x3 df64 matmuls, fixed s=5, straight-line.
//     Cuts the per-item serial chain ~2.5x vs one-lane-per-item df64.

#define MAXB (1 << 20)
#define TAU 262144.0f
__device__ int g_count;
__device__ int g_flag_idx[MAXB];

typedef unsigned long long u64;

// ---------------- packed f32x2 helpers (pass 1) ----------------
__device__ __forceinline__ u64 pk2(float lo, float hi) {
    u64 r;
    asm("mov.b64 %0, {%1, %2};" : "=l"(r) : "f"(lo), "f"(hi));
    return r;
}
__device__ __forceinline__ void upk2(u64 v, float& lo, float& hi) {
    asm("mov.b64 {%0, %1}, %2;" : "=f"(lo), "=f"(hi) : "l"(v));
}
__device__ __forceinline__ u64 fma2(u64 a, u64 b, u64 c) {
    u64 d;
    asm("fma.rn.f32x2 %0, %1, %2, %3;" : "=l"(d) : "l"(a), "l"(b), "l"(c));
    return d;
}
__device__ __forceinline__ u64 mul2(u64 a, u64 b) {
    u64 d;
    asm("mul.rn.f32x2 %0, %1, %2;" : "=l"(d) : "l"(a), "l"(b));
    return d;
}
__device__ __forceinline__ u64 add2(u64 a, u64 b) {
    u64 d;
    asm("add.rn.f32x2 %0, %1, %2;" : "=l"(d) : "l"(a), "l"(b));
    return d;
}

__device__ __forceinline__ void mm3p(const u64* __restrict__ a,
                                     const u64* __restrict__ b,
                                     u64* __restrict__ c) {
#pragma unroll
    for (int i = 0; i < 3; i++)
#pragma unroll
        for (int j = 0; j < 3; j++) {
            u64 s = mul2(a[i * 3], b[j]);
            s = fma2(a[i * 3 + 1], b[3 + j], s);
            s = fma2(a[i * 3 + 2], b[6 + j], s);
            c[i * 3 + j] = s;
        }
}

// ---------------- df64 (double-float) arithmetic (pass 2) ----------------
struct df { float h, l; };

__device__ __forceinline__ df two_sum(float a, float b) {
    float s = a + b;
    float bb = s - a;
    float e = (a - (s - bb)) + (b - bb);
    df r; r.h = s; r.l = e; return r;
}
__device__ __forceinline__ df quick2(float a, float b) {  // |a| >= |b|
    float s = a + b;
    float e = b - (s - a);
    df r; r.h = s; r.l = e; return r;
}
__device__ __forceinline__ df df_add(df a, df b) {
    df s = two_sum(a.h, b.h);
    s.l += (a.l + b.l);
    return quick2(s.h, s.l);
}
__device__ __forceinline__ df df_mul(df a, df b) {
    float p = a.h * b.h;
    float e = fmaf(a.h, b.h, -p);
    e = fmaf(a.h, b.l, fmaf(a.l, b.h, e));
    return quick2(p, e);
}
__device__ __forceinline__ df df_scale_pow2(df a, float p2) {
    df r; r.h = a.h * p2; r.l = a.l * p2; return r;
}
__device__ __forceinline__ df df_neg(df a) { df r; r.h = -a.h; r.l = -a.l; return r; }

#define DFC(x) df{(float)(x), (float)((x) - (double)(float)(x))}

// Compensated 3-term df dot product.
__device__ __forceinline__ df dot3(df a0, df b0, df a1, df b1, df a2, df b2) {
    float p1 = a0.h * b0.h;
    float e1 = fmaf(a0.h, b0.h, -p1);
    e1 = fmaf(a0.h, b0.l, fmaf(a0.l, b0.h, e1));
    float p2 = a1.h * b1.h;
    float e2 = fmaf(a1.h, b1.h, -p2);
    e2 = fmaf(a1.h, b1.l, fmaf(a1.l, b1.h, e2));
    float p3 = a2.h * b2.h;
    float e3 = fmaf(a2.h, b2.h, -p3);
    e3 = fmaf(a2.h, b2.l, fmaf(a2.l, b2.h, e3));

    df s1 = two_sum(p1, p2);
    df s2 = two_sum(s1.h, p3);
    float e = ((e1 + e2) + (e3 + s1.l)) + s2.l;
    return quick2(s2.h, e);
}

__device__ __forceinline__ df shfl_df(df v, int src) {
    df r;
    r.h = __shfl_sync(0xFFFFFFFFu, v.h, src);
    r.l = __shfl_sync(0xFFFFFFFFu, v.l, src);
    return r;
}

// Cooperative 3x3 df matmul: 3 lanes per item, lane holds one row.
// (c0,c1,c2) = row(X)*Y where (a0,a1,a2) = my row of X, (y0,y1,y2) = my row of Y.
__device__ __forceinline__ void coop_mm(df& c0, df& c1, df& c2,
                                        df a0, df a1, df a2,
                                        df y0, df y1, df y2, int base) {
    df Y00 = shfl_df(y0, base),     Y01 = shfl_df(y1, base),     Y02 = shfl_df(y2, base);
    df Y10 = shfl_df(y0, base + 1), Y11 = shfl_df(y1, base + 1), Y12 = shfl_df(y2, base + 1);
    df Y20 = shfl_df(y0, base + 2), Y21 = shfl_df(y1, base + 2), Y22 = shfl_df(y2, base + 2);
    c0 = dot3(a0, Y00, a1, Y10, a2, Y20);
    c1 = dot3(a0, Y01, a1, Y11, a2, Y21);
    c2 = dot3(a0, Y02, a1, Y12, a2, Y22);
}

__device__ __forceinline__ void expm_coop(const float* __restrict__ lie,
                                          float* __restrict__ out,
                                          int idx, int role, int base,
                                          bool active) {
    const float4* vp = reinterpret_cast<const float4*>(lie) + 2 * (size_t)idx;
    float4 v0 = vp[0];
    float4 v1 = vp[1];
    float x = v0.x, y = v0.y, r = v0.z, sc = v0.w;
    float st = v1.x, sh = v1.y, kx = v1.z, ky = v1.w;

    // My row of A (exact df via two_sum); branch-free-ish selection by role.
    float u0, w0, u1, w1, u2, w2;
    if (role == 0)      { u0 = sc; w0 = st;  u1 = sh; w1 = -r;  u2 = x;           w2 = 0.f; }
    else if (role == 1) { u0 = sh; w0 = r;   u1 = sc; w1 = -st; u2 = y;           w2 = 0.f; }
    else                { u0 = kx; w0 = 0.f; u1 = ky; w1 = 0.f; u2 = -2.0f * sc;  w2 = 0.f; }

    const float SCL = 0.03125f;  // 2^-5 (fixed s = 5; nrm <= 32 guaranteed)
    df A0 = df_scale_pow2(two_sum(u0, w0), SCL);
    df A1 = df_scale_pow2(two_sum(u1, w1), SCL);
    df A2 = df_scale_pow2(two_sum(u2, w2), SCL);

    df B0, B1, B2;  // row of A^2
    coop_mm(B0, B1, B2, A0, A1, A2, A0, A1, A2, base);
    df Z0, Z1, Z2;  // row of A^3 = A2 * A
    coop_mm(Z0, Z1, Z2, B0, B1, B2, A0, A1, A2, base);

    const df C2  = DFC(1.0 / 2.0);
    const df C3  = DFC(1.0 / 6.0);
    const df C4  = DFC(1.0 / 24.0);
    const df C5  = DFC(1.0 / 120.0);
    const df C6  = DFC(1.0 / 720.0);
    const df C7  = DFC(1.0 / 5040.0);
    const df C8  = DFC(1.0 / 40320.0);
    const df C9  = DFC(1.0 / 362880.0);
    const df C10 = DFC(1.0 / 3628800.0);
    const df C11 = DFC(1.0 / 39916800.0);
    const df ONE = df{1.0f, 0.0f};

    df P0, P1, P2, T0, T1, T2;

    // P = C3 = c9*I + c10*A + c11*A2
    P0 = df_add(df_mul(C10, A0), df_mul(C11, B0));
    P1 = df_add(df_mul(C10, A1), df_mul(C11, B1));
    P2 = df_add(df_mul(C10, A2), df_mul(C11, B2));
    if (role == 0) P0 = df_add(P0, C9);
    else if (role == 1) P1 = df_add(P1, C9);
    else P2 = df_add(P2, C9);

    coop_mm(T0, T1, T2, P0, P1, P2, Z0, Z1, Z2, base);
    P0 = df_add(T0, df_add(df_mul(C7, A0), df_mul(C8, B0)));
    P1 = df_add(T1, df_add(df_mul(C7, A1), df_mul(C8, B1)));
    P2 = df_add(T2, df_add(df_mul(C7, A2), df_mul(C8, B2)));
    if (role == 0) P0 = df_add(P0, C6);
    else if (role == 1) P1 = df_add(P1, C6);
    else P2 = df_add(P2, C6);

    coop_mm(T0, T1, T2, P0, P1, P2, Z0, Z1, Z2, base);
    P0 = df_add(T0, df_add(df_mul(C4, A0), df_mul(C5, B0)));
    P1 = df_add(T1, df_add(df_mul(C4, A1), df_mul(C5, B1)));
    P2 = df_add(T2, df_add(df_mul(C4, A2), df_mul(C5, B2)));
    if (role == 0) P0 = df_add(P0, C3);
    else if (role == 1) P1 = df_add(P1, C3);
    else P2 = df_add(P2, C3);

    coop_mm(T0, T1, T2, P0, P1, P2, Z0, Z1, Z2, base);
    P0 = df_add(T0, df_add(A0, df_mul(C2, B0)));
    P1 = df_add(T1, df_add(A1, df_mul(C2, B1)));
    P2 = df_add(T2, df_add(A2, df_mul(C2, B2)));
    if (role == 0) P0 = df_add(P0, ONE);
    else if (role == 1) P1 = df_add(P1, ONE);
    else P2 = df_add(P2, ONE);

    // Exactly 5 squarings.
#pragma unroll
    for (int q = 0; q < 5; q++) {
        coop_mm(T0, T1, T2, P0, P1, P2, P0, P1, P2, base);
        P0 = T0; P1 = T1; P2 = T2;
    }

    // H[2][2] lives in role-2 lane's third element.
    df p22 = shfl_df(P2, base + 2);

    // df64 reciprocal: fp32 seed + one df Newton step.
    float approx = 1.0f / p22.h;
    df e = df_mul(p22, df{approx, 0.f});
    df corr = df_add(df{2.0f, 0.0f}, df_neg(e));
    df rcp = df_mul(corr, df{approx, 0.f});

    if (active) {
        float* o = out + 9 * (size_t)idx + 3 * role;
        df q0 = df_mul(P0, rcp);
        df q1 = df_mul(P1, rcp);
        df q2 = df_mul(P2, rcp);
        o[0] = q0.h + q0.l;
        o[1] = q1.h + q1.l;
        o[2] = q2.h + q2.l;
    }
}

// ---------------- fp32 packed fast path ----------------
__global__ void __launch_bounds__(128)
pass1_f32x2_kernel(const float* __restrict__ lie, float* __restrict__ out, int n) {
    __shared__ float stage[128 * 18];

    int t = blockIdx.x * blockDim.x + threadIdx.x;
    int lane = threadIdx.x & 31;
    int warp = threadIdx.x >> 5;
    long long i0 = 2LL * t;
    long long i1 = i0 + 1;
    bool vlo = (i0 < n), vhi = (i1 < n);

    float4 a0 = make_float4(0.f, 0.f, 0.f, 0.f), a1 = a0, b0 = a0, b1 = a0;
    if (vlo) {
        const float4* vp = reinterpret_cast<const float4*>(lie) + 2 * i0;
        a0 = vp[0]; a1 = vp[1];
    }
    if (vhi) {
        const float4* vp = reinterpret_cast<const float4*>(lie) + 2 * i1;
        b0 = vp[0]; b1 = vp[1];
    }

    const float SCL = 0.125f;  // fixed s = 3

    float AL[9], AH[9];
    AL[0] = (a0.w + a1.x) * SCL; AL[1] = (a1.y - a0.z) * SCL; AL[2] = a0.x * SCL;
    AL[3] = (a1.y + a0.z) * SCL; AL[4] = (a0.w - a1.x) * SCL; AL[5] = a0.y * SCL;
    AL[6] = a1.z * SCL;          AL[7] = a1.w * SCL;          AL[8] = -2.0f * a0.w * SCL;

    AH[0] = (b0.w + b1.x) * SCL; AH[1] = (b1.y - b0.z) * SCL; AH[2] = b0.x * SCL;
    AH[3] = (b1.y + b0.z) * SCL; AH[4] = (b0.w - b1.x) * SCL; AH[5] = b0.y * SCL;
    AH[6] = b1.z * SCL;          AH[7] = b1.w * SCL;          AH[8] = -2.0f * b0.w * SCL;

    float nl = fmaxf(fabsf(AL[0]) + fabsf(AL[1]) + fabsf(AL[2]),
               fmaxf(fabsf(AL[3]) + fabsf(AL[4]) + fabsf(AL[5]),
                     fabsf(AL[6]) + fabsf(AL[7]) + fabsf(AL[8])));
    float nh = fmaxf(fabsf(AH[0]) + fabsf(AH[1]) + fabsf(AH[2]),
               fmaxf(fabsf(AH[3]) + fabsf(AH[4]) + fabsf(AH[5]),
                     fabsf(AH[6]) + fabsf(AH[7]) + fabsf(AH[8])));

    u64 A[9];
#pragma unroll
    for (int k = 0; k < 9; k++) A[k] = pk2(AL[k], AH[k]);

    u64 A2[9], A3[9];
    mm3p(A, A, A2);
    mm3p(A2, A, A3);

    const u64 C2  = pk2(1.0f / 2, 1.0f / 2);
    const u64 C3  = pk2(1.0f / 6, 1.0f / 6);
    const u64 C4  = pk2(1.0f / 24, 1.0f / 24);
    const u64 C5  = pk2(1.0f / 120, 1.0f / 120);
    const u64 C6  = pk2(1.0f / 720, 1.0f / 720);
    const u64 C7  = pk2(1.0f / 5040, 1.0f / 5040);
    const u64 C8  = pk2(1.0f / 40320, 1.0f / 40320);
    const u64 C9  = pk2(1.0f / 362880, 1.0f / 362880);
    const u64 C10 = pk2(1.0f / 3628800, 1.0f / 3628800);
    const u64 C11 = pk2(1.0f / 39916800, 1.0f / 39916800);
    const u64 ONE = pk2(1.0f, 1.0f);

    u64 P[9], T[9];
#pragma unroll
    for (int k = 0; k < 9; k++) P[k] = fma2(C10, A[k], mul2(C11, A2[k]));
    P[0] = add2(P[0], C9); P[4] = add2(P[4], C9); P[8] = add2(P[8], C9);

    mm3p(P, A3, T);
#pragma unroll
    for (int k = 0; k < 9; k++) P[k] = fma2(C7, A[k], fma2(C8, A2[k], T[k]));
    P[0] = add2(P[0], C6); P[4] = add2(P[4], C6); P[8] = add2(P[8], C6);

    mm3p(P, A3, T);
#pragma unroll
    for (int k = 0; k < 9; k++) P[k] = fma2(C4, A[k], fma2(C5, A2[k], T[k]));
    P[0] = add2(P[0], C3); P[4] = add2(P[4], C3); P[8] = add2(P[8], C3);

    mm3p(P, A3, T);
#pragma unroll
    for (int k = 0; k < 9; k++) P[k] = fma2(C2, A2[k], add2(T[k], A[k]));
    P[0] = add2(P[0], ONE); P[4] = add2(P[4], ONE); P[8] = add2(P[8], ONE);

    mm3p(P, P, T);
    mm3p(T, T, P);
    mm3p(P, P, T);

    float HL[9], HH[9];
#pragma unroll
    for (int k = 0; k < 9; k++) upk2(T[k], HL[k], HH[k]);

    float mxl = 0.0f, mxh = 0.0f;
#pragma unroll
    for (int k = 0; k < 9; k++) {
        mxl = fmaxf(mxl, fabsf(HL[k]));
        mxh = fmaxf(mxh, fabsf(HH[k]));
    }
    bool flag_lo = vlo && !((nl <= 2.0f) && (8.0f * mxl <= TAU * fabsf(HL[8])));
    bool flag_hi = vhi && !((nh <= 2.0f) && (8.0f * mxh <= TAU * fabsf(HH[8])));

    unsigned blo = __ballot_sync(0xFFFFFFFFu, flag_lo);
    if (blo) {
        int leader = __ffs(blo) - 1;
        int base = 0;
        if (lane == leader) base = atomicAdd(&g_count, __popc(blo));
        base = __shfl_sync(0xFFFFFFFFu, base, leader);
        if (flag_lo) {
            int slot = base + __popc(blo & ((1u << lane) - 1u));
            if (slot < MAXB) g_flag_idx[slot] = (int)i0;
        }
    }
    unsigned bhi = __ballot_sync(0xFFFFFFFFu, flag_hi);
    if (bhi) {
        int leader = __ffs(bhi) - 1;
        int base = 0;
        if (lane == leader) base = atomicAdd(&g_count, __popc(bhi));
        base = __shfl_sync(0xFFFFFFFFu, base, leader);
        if (flag_hi) {
            int slot = base + __popc(bhi & ((1u << lane) - 1u));
            if (slot < MAXB) g_flag_idx[slot] = (int)i1;
        }
    }

    float invl = 1.0f / HL[8];
    float invh = 1.0f / HH[8];
    float* ws = stage + warp * 576;
#pragma unroll
    for (int k = 0; k < 9; k++) {
        ws[lane * 18 + k] = HL[k] * invl;
        ws[lane * 18 + 9 + k] = HH[k] * invh;
    }
    __syncwarp();

    long long wstart = 2LL * ((long long)blockIdx.x * blockDim.x + warp * 32);
    long long rem = (long long)n - wstart;
    int vcount = (rem > 64) ? 64 : (rem > 0 ? (int)rem : 0);
    if (vcount > 0) {
        float* o = out + 9 * wstart;
        int total = vcount * 9;
        for (int j = lane; j < total; j += 32) o[j] = ws[j];
    }
}

__global__ void __launch_bounds__(64)
pass2_coop_kernel(const float* __restrict__ lie, float* __restrict__ out) {
    int cnt = g_count;
    if (cnt > MAXB) cnt = MAXB;

    int lane = threadIdx.x & 31;
    int grp = lane / 3;            // 0..9 active groups, grp==10 idle (lanes 30,31)
    int role = lane - grp * 3;
    int base = grp * 3;

    int wpb = blockDim.x >> 5;
    int gwarp = blockIdx.x * wpb + (threadIdx.x >> 5);
    int nwarp = gridDim.x * wpb;

    for (int it0 = gwarp * 10; it0 < cnt; it0 += nwarp * 10) {
        int item = it0 + grp;
        bool active = (grp < 10) && (item < cnt);
        int idx = active ? g_flag_idx[item] : 0;
        expm_coop(lie, out, idx, role, base, active);
    }
}

extern "C" void kernel_launch(void* const* d_in, const int* in_sizes, int n_in,
                              void* d_out, int out_size) {
    const float* lie = (const float*)d_in[0];
    float* out = (float*)d_out;
    int n = in_sizes[0] / 8;

    void* cnt_addr = nullptr;
    cudaGetSymbolAddress(&cnt_addr, g_count);
    cudaMemsetAsync(cnt_addr, 0, sizeof(int));

    int threads = 128;
    int items_per_block = threads * 2;
    int blocks = (n + items_per_block - 1) / items_per_block;
    pass1_f32x2_kernel<<<blocks, threads>>>(lie, out, n);
    pass2_coop_kernel<<<1024, 64>>>(lie, out);
}